// round 5
// baseline (speedup 1.0000x reference)
#include <cuda_runtime.h>
#include <cstdint>

// Problem constants (all shapes fixed by setup_inputs)
#define B_WIN   4096
#define NTOK    49
#define C_DIM   192
#define NHEAD   6
#define DHEAD   32
#define NWIN    64
#define M_TOTAL (B_WIN * NTOK)     // 200704 = 128 * 1568
#define QKV_N   (3 * C_DIM)        // 576

// Scratch: __device__ globals (allocation-guard-safe)
__device__ float g_qkv[(size_t)M_TOTAL * QKV_N];   // ~462 MB
__device__ float g_att[(size_t)M_TOTAL * C_DIM];   // ~154 MB

// ---------------------------------------------------------------------------
// Generic fp32 tiled GEMM: C[M,N] = A[M,K] @ B[K,N] (+ bias[N])
// BM=128, BN=64, BK=16, 256 threads, 8x4 register tile per thread.
// Requires: M % 128 == 0, N % 64 == 0, K % 16 == 0 (true for all our shapes).
// ---------------------------------------------------------------------------
#define BM 128
#define BN 64
#define BK 16
#define TM 8
#define TN 4

__global__ __launch_bounds__(256)
void gemm_kernel(const float* __restrict__ A, const float* __restrict__ Bm,
                 float* __restrict__ Cm, const float* __restrict__ bias,
                 int M, int N, int K)
{
    __shared__ __align__(16) float As[BK][BM];   // A transposed tile
    __shared__ __align__(16) float Bs[BK][BN];

    const int tid  = threadIdx.x;          // 0..255
    const int tcol = tid & 15;             // 0..15 -> 4-col group
    const int trow = tid >> 4;             // 0..15 -> 8-row group
    const int m0 = blockIdx.x * BM;
    const int n0 = blockIdx.y * BN;

    float acc[TM][TN];
#pragma unroll
    for (int i = 0; i < TM; i++)
#pragma unroll
        for (int j = 0; j < TN; j++) acc[i][j] = 0.0f;

    for (int k0 = 0; k0 < K; k0 += BK) {
        // Load A tile (BM x BK) transposed into As[BK][BM]: 512 float4s
#pragma unroll
        for (int f = tid; f < BM * BK / 4; f += 256) {
            int m  = f >> 2;           // 0..127
            int kq = f & 3;            // 0..3 (float4 group along K)
            const float4 a4 = *reinterpret_cast<const float4*>(
                A + (size_t)(m0 + m) * K + k0 + kq * 4);
            As[kq * 4 + 0][m] = a4.x;
            As[kq * 4 + 1][m] = a4.y;
            As[kq * 4 + 2][m] = a4.z;
            As[kq * 4 + 3][m] = a4.w;
        }
        // Load B tile (BK x BN): 256 float4s
        {
            int f = tid;               // 0..255 exactly covers 16x16 float4s
            int kr = f >> 4;           // 0..15
            int nq = f & 15;           // 0..15
            const float4 b4 = *reinterpret_cast<const float4*>(
                Bm + (size_t)(k0 + kr) * N + n0 + nq * 4);
            *reinterpret_cast<float4*>(&Bs[kr][nq * 4]) = b4;
        }
        __syncthreads();

#pragma unroll
        for (int kk = 0; kk < BK; kk++) {
            float a[TM], b[TN];
            const float4 a0 = *reinterpret_cast<const float4*>(&As[kk][trow * TM + 0]);
            const float4 a1 = *reinterpret_cast<const float4*>(&As[kk][trow * TM + 4]);
            a[0]=a0.x; a[1]=a0.y; a[2]=a0.z; a[3]=a0.w;
            a[4]=a1.x; a[5]=a1.y; a[6]=a1.z; a[7]=a1.w;
            const float4 b0 = *reinterpret_cast<const float4*>(&Bs[kk][tcol * TN]);
            b[0]=b0.x; b[1]=b0.y; b[2]=b0.z; b[3]=b0.w;
#pragma unroll
            for (int i = 0; i < TM; i++)
#pragma unroll
                for (int j = 0; j < TN; j++)
                    acc[i][j] = fmaf(a[i], b[j], acc[i][j]);
        }
        __syncthreads();
    }

    // Epilogue
    float4 bv = make_float4(0.f, 0.f, 0.f, 0.f);
    if (bias) bv = *reinterpret_cast<const float4*>(bias + n0 + tcol * TN);
#pragma unroll
    for (int i = 0; i < TM; i++) {
        const int row = m0 + trow * TM + i;
        float4 o;
        o.x = acc[i][0] + bv.x;
        o.y = acc[i][1] + bv.y;
        o.z = acc[i][2] + bv.z;
        o.w = acc[i][3] + bv.w;
        *reinterpret_cast<float4*>(Cm + (size_t)row * N + n0 + tcol * TN) = o;
    }
}

// ---------------------------------------------------------------------------
// Fused attention: one block per (window b, head h).
//   q,k,v from g_qkv; S = q k^T * scale + mask[b % 64]; softmax; O = P v
// ---------------------------------------------------------------------------
__global__ __launch_bounds__(128)
void attn_kernel(const float* __restrict__ mask)
{
    __shared__ float qs[NTOK][DHEAD + 1];
    __shared__ float ks[NTOK][DHEAD + 1];
    __shared__ float vs[NTOK][DHEAD];
    __shared__ float ss[NTOK][NTOK];

    const int blk = blockIdx.x;
    const int b = blk / NHEAD;
    const int h = blk % NHEAD;
    const int tid = threadIdx.x;           // 128 threads
    const float scale = 0.17677669529663687f;   // 32^{-1/2}

    const size_t base = (size_t)b * NTOK * QKV_N;
    const int qc = h * DHEAD;
    const int kc = C_DIM + h * DHEAD;
    const int vc = 2 * C_DIM + h * DHEAD;

    // Load q (pre-scaled), k, v
    for (int e = tid; e < NTOK * DHEAD; e += 128) {
        const int i = e >> 5, d = e & 31;
        const float* row = g_qkv + base + (size_t)i * QKV_N;
        qs[i][d] = row[qc + d] * scale;
        ks[i][d] = row[kc + d];
        vs[i][d] = row[vc + d];
    }
    __syncthreads();

    // S = q k^T + mask   (16 threads per row, 8 rows in flight)
    const float* mrow = mask + (size_t)(b & (NWIN - 1)) * NTOK * NTOK;
    const int lane16 = tid & 15;
    const int rgrp   = tid >> 4;
    for (int i = rgrp; i < NTOK; i += 8) {
        const int j0 = lane16, j1 = lane16 + 16, j2 = lane16 + 32;
        float a0 = 0.f, a1 = 0.f, a2 = 0.f, a3 = 0.f;
#pragma unroll
        for (int d = 0; d < DHEAD; d++) {
            const float qv = qs[i][d];
            a0 = fmaf(qv, ks[j0][d], a0);
            a1 = fmaf(qv, ks[j1][d], a1);
            a2 = fmaf(qv, ks[j2][d], a2);
            a3 = fmaf(qv, ks[48][d], a3);      // column 48, redundant across lanes
        }
        ss[i][j0] = a0 + mrow[i * NTOK + j0];
        ss[i][j1] = a1 + mrow[i * NTOK + j1];
        ss[i][j2] = a2 + mrow[i * NTOK + j2];
        if (lane16 == 0) ss[i][48] = a3 + mrow[i * NTOK + 48];
    }
    __syncthreads();

    // Row softmax (threads 0..48, each one full row)
    if (tid < NTOK) {
        float mx = -1e30f;
#pragma unroll
        for (int j = 0; j < NTOK; j++) mx = fmaxf(mx, ss[tid][j]);
        float sum = 0.f;
#pragma unroll
        for (int j = 0; j < NTOK; j++) {
            const float e = __expf(ss[tid][j] - mx);
            ss[tid][j] = e;
            sum += e;
        }
        const float inv = 1.0f / sum;
#pragma unroll
        for (int j = 0; j < NTOK; j++) ss[tid][j] *= inv;
    }
    __syncthreads();

    // O = P V  -> g_att[b, i, h*32 + d]
    for (int e = tid; e < NTOK * DHEAD; e += 128) {
        const int i = e >> 5, d = e & 31;
        float acc = 0.f;
#pragma unroll
        for (int j = 0; j < NTOK; j++)
            acc = fmaf(ss[i][j], vs[j][d], acc);
        g_att[(size_t)(b * NTOK + i) * C_DIM + h * DHEAD + d] = acc;
    }
}

// ---------------------------------------------------------------------------
// Launch: QKV GEMM -> attention -> projection GEMM (+bias)
// ---------------------------------------------------------------------------
extern "C" void kernel_launch(void* const* d_in, const int* in_sizes, int n_in,
                              void* d_out, int out_size)
{
    const float* x      = (const float*)d_in[0];
    const float* mask   = (const float*)d_in[1];
    const float* w_qkv  = (const float*)d_in[2];
    const float* w_proj = (const float*)d_in[3];
    const float* b_proj = (const float*)d_in[4];
    float* out = (float*)d_out;

    float *qkv_ptr, *att_ptr;
    cudaGetSymbolAddress((void**)&qkv_ptr, g_qkv);
    cudaGetSymbolAddress((void**)&att_ptr, g_att);

    // QKV: [200704,192] @ [192,576]
    gemm_kernel<<<dim3(M_TOTAL / BM, QKV_N / BN), 256>>>(
        x, w_qkv, qkv_ptr, nullptr, M_TOTAL, QKV_N, C_DIM);

    // Attention per (window, head)
    attn_kernel<<<B_WIN * NHEAD, 128>>>(mask);

    // Projection: [200704,192] @ [192,192] + bias
    gemm_kernel<<<dim3(M_TOTAL / BM, C_DIM / BN), 256>>>(
        att_ptr, w_proj, out, b_proj, M_TOTAL, C_DIM, C_DIM);
}

// round 7
// speedup vs baseline: 1.3327x; 1.3327x over previous
#include <cuda_runtime.h>
#include <cstdint>

// Problem constants (fixed by setup_inputs)
#define B_WIN   4096
#define NTOK    49
#define C_DIM   192
#define NHEAD   6
#define DHEAD   32
#define NWIN    64
#define M_TOTAL (B_WIN * NTOK)     // 200704 = 128 * 1568
#define QKV_N   576
#define KDIM    192                // K for BOTH gemms (x and g_att have 192 cols)

// Scratch (__device__ globals: allocation-guard-safe)
__device__ float g_qkv[(size_t)M_TOTAL * QKV_N];
__device__ float g_att[(size_t)M_TOTAL * C_DIM];

__device__ __forceinline__ uint32_t f2tf32(float f) {
    uint32_t r;
    asm("cvt.rna.tf32.f32 %0, %1;" : "=r"(r) : "f"(f));
    return r;
}

__device__ __forceinline__ void mma_tf32(float* c, const uint32_t* a, const uint32_t* b) {
    asm volatile(
        "mma.sync.aligned.m16n8k8.row.col.f32.tf32.tf32.f32 "
        "{%0,%1,%2,%3}, {%4,%5,%6,%7}, {%8,%9}, {%0,%1,%2,%3};"
        : "+f"(c[0]), "+f"(c[1]), "+f"(c[2]), "+f"(c[3])
        : "r"(a[0]), "r"(a[1]), "r"(a[2]), "r"(a[3]), "r"(b[0]), "r"(b[1]));
}

// ---------------------------------------------------------------------------
// tf32 mma.sync GEMM:  C[M_TOTAL, N] = A[M_TOTAL, 192] @ W[192, N]  (+bias)
// CTA tile 128x64, BK=32, 256 threads (8 warps, 4x2 warp grid, 32x32/warp).
// W consumed directly in row-major [K][N] form (no pre-transpose needed).
// ---------------------------------------------------------------------------
#define BM 128
#define BN 64
#define BK 32
#define APITCH (BM + 8)   // 136: 136 % 32 == 8 -> conflict-free A frag LDS
#define BPITCH (BN + 8)   // 72:   72 % 32 == 8 -> conflict-free B frag LDS

__global__ __launch_bounds__(256)
void mma_gemm(const float* __restrict__ A, const float* __restrict__ W,
              float* __restrict__ C, const float* __restrict__ bias, int N)
{
    __shared__ uint32_t As[BK][APITCH];   // [k][m], tf32 bits
    __shared__ uint32_t Bs[BK][BPITCH];   // [k][n], tf32 bits

    const int tid  = threadIdx.x;
    const int wid  = tid >> 5;
    const int lane = tid & 31;
    const int grp  = lane >> 2;      // 0..7
    const int quad = lane & 3;       // 0..3
    const int wm   = wid & 3;        // 4 m-warps (32 rows each)
    const int wn   = wid >> 2;       // 2 n-warps (32 cols each)
    const int m0   = blockIdx.y * BM;
    const int n0   = blockIdx.x * BN;

    float acc[2][4][4];
#pragma unroll
    for (int mt = 0; mt < 2; mt++)
#pragma unroll
        for (int nt = 0; nt < 4; nt++)
#pragma unroll
            for (int r = 0; r < 4; r++) acc[mt][nt][r] = 0.0f;

    for (int k0 = 0; k0 < KDIM; k0 += BK) {
        // A tile: 128 rows x 32 k  (8 float4 per row -> 1024 float4, 4/thread)
#pragma unroll
        for (int f = tid; f < BM * 8; f += 256) {
            const int m  = f >> 3;
            const int kq = f & 7;
            const float4 v = *reinterpret_cast<const float4*>(
                A + (size_t)(m0 + m) * KDIM + k0 + kq * 4);
            As[kq * 4 + 0][m] = f2tf32(v.x);
            As[kq * 4 + 1][m] = f2tf32(v.y);
            As[kq * 4 + 2][m] = f2tf32(v.z);
            As[kq * 4 + 3][m] = f2tf32(v.w);
        }
        // B tile: 32 k-rows x 64 n  (16 float4 per row -> 512 float4, 2/thread)
#pragma unroll
        for (int f = tid; f < BK * 16; f += 256) {
            const int k  = f >> 4;
            const int nq = f & 15;
            const float4 v = *reinterpret_cast<const float4*>(
                W + (size_t)(k0 + k) * N + n0 + nq * 4);
            Bs[k][nq * 4 + 0] = f2tf32(v.x);
            Bs[k][nq * 4 + 1] = f2tf32(v.y);
            Bs[k][nq * 4 + 2] = f2tf32(v.z);
            Bs[k][nq * 4 + 3] = f2tf32(v.w);
        }
        __syncthreads();

#pragma unroll
        for (int ks = 0; ks < BK / 8; ks++) {
            const int k = ks * 8;
            uint32_t a[2][4], b[4][2];
#pragma unroll
            for (int mt = 0; mt < 2; mt++) {
                const int r0 = wm * 32 + mt * 16 + grp;
                a[mt][0] = As[k + quad    ][r0];
                a[mt][1] = As[k + quad    ][r0 + 8];
                a[mt][2] = As[k + quad + 4][r0];
                a[mt][3] = As[k + quad + 4][r0 + 8];
            }
#pragma unroll
            for (int nt = 0; nt < 4; nt++) {
                const int n = wn * 32 + nt * 8 + grp;
                b[nt][0] = Bs[k + quad    ][n];
                b[nt][1] = Bs[k + quad + 4][n];
            }
#pragma unroll
            for (int mt = 0; mt < 2; mt++)
#pragma unroll
                for (int nt = 0; nt < 4; nt++)
                    mma_tf32(acc[mt][nt], a[mt], b[nt]);
        }
        __syncthreads();
    }

    // Epilogue: direct stores. Each lane-quad writes a contiguous 32B sector.
#pragma unroll
    for (int mt = 0; mt < 2; mt++) {
#pragma unroll
        for (int nt = 0; nt < 4; nt++) {
            const int row = m0 + wm * 32 + mt * 16 + grp;
            const int col = n0 + wn * 32 + nt * 8 + quad * 2;
            float b0 = 0.f, b1 = 0.f;
            if (bias) { b0 = bias[col]; b1 = bias[col + 1]; }
            float2 v0 = make_float2(acc[mt][nt][0] + b0, acc[mt][nt][1] + b1);
            float2 v1 = make_float2(acc[mt][nt][2] + b0, acc[mt][nt][3] + b1);
            *reinterpret_cast<float2*>(C + (size_t)row * N + col) = v0;
            *reinterpret_cast<float2*>(C + (size_t)(row + 8) * N + col) = v1;
        }
    }
}

// ---------------------------------------------------------------------------
// Fused attention (unchanged, validated in R5): one block per (window, head)
// ---------------------------------------------------------------------------
__global__ __launch_bounds__(128)
void attn_kernel(const float* __restrict__ mask)
{
    __shared__ float qs[NTOK][DHEAD + 1];
    __shared__ float ks[NTOK][DHEAD + 1];
    __shared__ float vs[NTOK][DHEAD];
    __shared__ float ss[NTOK][NTOK];

    const int blk = blockIdx.x;
    const int b = blk / NHEAD;
    const int h = blk % NHEAD;
    const int tid = threadIdx.x;
    const float scale = 0.17677669529663687f;

    const size_t base = (size_t)b * NTOK * QKV_N;
    const int qc = h * DHEAD;
    const int kc = C_DIM + h * DHEAD;
    const int vc = 2 * C_DIM + h * DHEAD;

    for (int e = tid; e < NTOK * DHEAD; e += 128) {
        const int i = e >> 5, d = e & 31;
        const float* row = g_qkv + base + (size_t)i * QKV_N;
        qs[i][d] = row[qc + d] * scale;
        ks[i][d] = row[kc + d];
        vs[i][d] = row[vc + d];
    }
    __syncthreads();

    const float* mrow = mask + (size_t)(b & (NWIN - 1)) * NTOK * NTOK;
    const int lane16 = tid & 15;
    const int rgrp   = tid >> 4;
    for (int i = rgrp; i < NTOK; i += 8) {
        const int j0 = lane16, j1 = lane16 + 16, j2 = lane16 + 32;
        float a0 = 0.f, a1 = 0.f, a2 = 0.f, a3 = 0.f;
#pragma unroll
        for (int d = 0; d < DHEAD; d++) {
            const float qv = qs[i][d];
            a0 = fmaf(qv, ks[j0][d], a0);
            a1 = fmaf(qv, ks[j1][d], a1);
            a2 = fmaf(qv, ks[j2][d], a2);
            a3 = fmaf(qv, ks[48][d], a3);
        }
        ss[i][j0] = a0 + mrow[i * NTOK + j0];
        ss[i][j1] = a1 + mrow[i * NTOK + j1];
        ss[i][j2] = a2 + mrow[i * NTOK + j2];
        if (lane16 == 0) ss[i][48] = a3 + mrow[i * NTOK + 48];
    }
    __syncthreads();

    if (tid < NTOK) {
        float mx = -1e30f;
#pragma unroll
        for (int j = 0; j < NTOK; j++) mx = fmaxf(mx, ss[tid][j]);
        float sum = 0.f;
#pragma unroll
        for (int j = 0; j < NTOK; j++) {
            const float e = __expf(ss[tid][j] - mx);
            ss[tid][j] = e;
            sum += e;
        }
        const float inv = 1.0f / sum;
#pragma unroll
        for (int j = 0; j < NTOK; j++) ss[tid][j] *= inv;
    }
    __syncthreads();

    for (int e = tid; e < NTOK * DHEAD; e += 128) {
        const int i = e >> 5, d = e & 31;
        float acc = 0.f;
#pragma unroll
        for (int j = 0; j < NTOK; j++)
            acc = fmaf(ss[i][j], vs[j][d], acc);
        g_att[(size_t)(b * NTOK + i) * C_DIM + h * DHEAD + d] = acc;
    }
}

// ---------------------------------------------------------------------------
// Launch pipeline: QKV GEMM -> attention -> projection GEMM (+bias)
// ---------------------------------------------------------------------------
extern "C" void kernel_launch(void* const* d_in, const int* in_sizes, int n_in,
                              void* d_out, int out_size)
{
    const float* x      = (const float*)d_in[0];
    const float* mask   = (const float*)d_in[1];
    const float* w_qkv  = (const float*)d_in[2];
    const float* w_proj = (const float*)d_in[3];
    const float* b_proj = (const float*)d_in[4];
    float* out = (float*)d_out;

    float *qkvp, *attp;
    cudaGetSymbolAddress((void**)&qkvp, g_qkv);
    cudaGetSymbolAddress((void**)&attp, g_att);

    // QKV: [200704,192] @ [192,576]   (grid.x = N-blocks -> A-tile L2 reuse)
    mma_gemm<<<dim3(QKV_N / BN, M_TOTAL / BM), 256>>>(x, w_qkv, qkvp, nullptr, QKV_N);

    // Attention per (window, head)
    attn_kernel<<<B_WIN * NHEAD, 128>>>(mask);

    // Proj: [200704,192] @ [192,192] + bias
    mma_gemm<<<dim3(C_DIM / BN, M_TOTAL / BM), 256>>>(attp, w_proj, out, b_proj, C_DIM);
}

// round 8
// speedup vs baseline: 1.3349x; 1.0017x over previous
#include <cuda_runtime.h>
#include <cstdint>

// Problem constants (fixed by setup_inputs)
#define B_WIN   4096
#define NTOK    49
#define C_DIM   192
#define NHEAD   6
#define DHEAD   32
#define NWIN    64
#define M_TOTAL (B_WIN * NTOK)     // 200704 = 128 * 1568
#define QKV_N   576
#define KDIM    192                // K for BOTH gemms (x and g_att have 192 cols)

// Scratch (__device__ globals: allocation-guard-safe)
__device__ float g_qkv[(size_t)M_TOTAL * QKV_N];
__device__ float g_att[(size_t)M_TOTAL * C_DIM];

__device__ __forceinline__ uint32_t f2tf32(float f) {
    uint32_t r;
    asm("cvt.rna.tf32.f32 %0, %1;" : "=r"(r) : "f"(f));
    return r;
}

__device__ __forceinline__ void mma_tf32(float* c, const uint32_t* a, const uint32_t* b) {
    asm volatile(
        "mma.sync.aligned.m16n8k8.row.col.f32.tf32.tf32.f32 "
        "{%0,%1,%2,%3}, {%4,%5,%6,%7}, {%8,%9}, {%0,%1,%2,%3};"
        : "+f"(c[0]), "+f"(c[1]), "+f"(c[2]), "+f"(c[3])
        : "r"(a[0]), "r"(a[1]), "r"(a[2]), "r"(a[3]), "r"(b[0]), "r"(b[1]));
}

// ---------------------------------------------------------------------------
// tf32 mma.sync GEMM:  C[M_TOTAL, N] = A[M_TOTAL, 192] @ W[192, N]  (+bias)
// CTA tile 128x64, BK=32, 256 threads (8 warps, 4x2 warp grid, 32x32/warp).
// W consumed directly in row-major [K][N] form (no pre-transpose needed).
// ---------------------------------------------------------------------------
#define BM 128
#define BN 64
#define BK 32
#define APITCH (BM + 8)   // 136: 136 % 32 == 8 -> conflict-free A frag LDS
#define BPITCH (BN + 8)   // 72:   72 % 32 == 8 -> conflict-free B frag LDS

__global__ __launch_bounds__(256)
void mma_gemm(const float* __restrict__ A, const float* __restrict__ W,
              float* __restrict__ C, const float* __restrict__ bias, int N)
{
    __shared__ uint32_t As[BK][APITCH];   // [k][m], tf32 bits
    __shared__ uint32_t Bs[BK][BPITCH];   // [k][n], tf32 bits

    const int tid  = threadIdx.x;
    const int wid  = tid >> 5;
    const int lane = tid & 31;
    const int grp  = lane >> 2;      // 0..7
    const int quad = lane & 3;       // 0..3
    const int wm   = wid & 3;        // 4 m-warps (32 rows each)
    const int wn   = wid >> 2;       // 2 n-warps (32 cols each)
    const int m0   = blockIdx.y * BM;
    const int n0   = blockIdx.x * BN;

    float acc[2][4][4];
#pragma unroll
    for (int mt = 0; mt < 2; mt++)
#pragma unroll
        for (int nt = 0; nt < 4; nt++)
#pragma unroll
            for (int r = 0; r < 4; r++) acc[mt][nt][r] = 0.0f;

    for (int k0 = 0; k0 < KDIM; k0 += BK) {
        // A tile: 128 rows x 32 k  (8 float4 per row -> 1024 float4, 4/thread)
#pragma unroll
        for (int f = tid; f < BM * 8; f += 256) {
            const int m  = f >> 3;
            const int kq = f & 7;
            const float4 v = *reinterpret_cast<const float4*>(
                A + (size_t)(m0 + m) * KDIM + k0 + kq * 4);
            As[kq * 4 + 0][m] = f2tf32(v.x);
            As[kq * 4 + 1][m] = f2tf32(v.y);
            As[kq * 4 + 2][m] = f2tf32(v.z);
            As[kq * 4 + 3][m] = f2tf32(v.w);
        }
        // B tile: 32 k-rows x 64 n  (16 float4 per row -> 512 float4, 2/thread)
#pragma unroll
        for (int f = tid; f < BK * 16; f += 256) {
            const int k  = f >> 4;
            const int nq = f & 15;
            const float4 v = *reinterpret_cast<const float4*>(
                W + (size_t)(k0 + k) * N + n0 + nq * 4);
            Bs[k][nq * 4 + 0] = f2tf32(v.x);
            Bs[k][nq * 4 + 1] = f2tf32(v.y);
            Bs[k][nq * 4 + 2] = f2tf32(v.z);
            Bs[k][nq * 4 + 3] = f2tf32(v.w);
        }
        __syncthreads();

#pragma unroll
        for (int ks = 0; ks < BK / 8; ks++) {
            const int k = ks * 8;
            uint32_t a[2][4], b[4][2];
#pragma unroll
            for (int mt = 0; mt < 2; mt++) {
                const int r0 = wm * 32 + mt * 16 + grp;
                a[mt][0] = As[k + quad    ][r0];
                a[mt][1] = As[k + quad    ][r0 + 8];
                a[mt][2] = As[k + quad + 4][r0];
                a[mt][3] = As[k + quad + 4][r0 + 8];
            }
#pragma unroll
            for (int nt = 0; nt < 4; nt++) {
                const int n = wn * 32 + nt * 8 + grp;
                b[nt][0] = Bs[k + quad    ][n];
                b[nt][1] = Bs[k + quad + 4][n];
            }
#pragma unroll
            for (int mt = 0; mt < 2; mt++)
#pragma unroll
                for (int nt = 0; nt < 4; nt++)
                    mma_tf32(acc[mt][nt], a[mt], b[nt]);
        }
        __syncthreads();
    }

    // Epilogue: direct stores. Each lane-quad writes a contiguous 32B sector.
#pragma unroll
    for (int mt = 0; mt < 2; mt++) {
#pragma unroll
        for (int nt = 0; nt < 4; nt++) {
            const int row = m0 + wm * 32 + mt * 16 + grp;
            const int col = n0 + wn * 32 + nt * 8 + quad * 2;
            float b0 = 0.f, b1 = 0.f;
            if (bias) { b0 = bias[col]; b1 = bias[col + 1]; }
            float2 v0 = make_float2(acc[mt][nt][0] + b0, acc[mt][nt][1] + b1);
            float2 v1 = make_float2(acc[mt][nt][2] + b0, acc[mt][nt][3] + b1);
            *reinterpret_cast<float2*>(C + (size_t)row * N + col) = v0;
            *reinterpret_cast<float2*>(C + (size_t)(row + 8) * N + col) = v1;
        }
    }
}

// ---------------------------------------------------------------------------
// Fused attention (unchanged, validated in R5): one block per (window, head)
// ---------------------------------------------------------------------------
__global__ __launch_bounds__(128)
void attn_kernel(const float* __restrict__ mask)
{
    __shared__ float qs[NTOK][DHEAD + 1];
    __shared__ float ks[NTOK][DHEAD + 1];
    __shared__ float vs[NTOK][DHEAD];
    __shared__ float ss[NTOK][NTOK];

    const int blk = blockIdx.x;
    const int b = blk / NHEAD;
    const int h = blk % NHEAD;
    const int tid = threadIdx.x;
    const float scale = 0.17677669529663687f;

    const size_t base = (size_t)b * NTOK * QKV_N;
    const int qc = h * DHEAD;
    const int kc = C_DIM + h * DHEAD;
    const int vc = 2 * C_DIM + h * DHEAD;

    for (int e = tid; e < NTOK * DHEAD; e += 128) {
        const int i = e >> 5, d = e & 31;
        const float* row = g_qkv + base + (size_t)i * QKV_N;
        qs[i][d] = row[qc + d] * scale;
        ks[i][d] = row[kc + d];
        vs[i][d] = row[vc + d];
    }
    __syncthreads();

    const float* mrow = mask + (size_t)(b & (NWIN - 1)) * NTOK * NTOK;
    const int lane16 = tid & 15;
    const int rgrp   = tid >> 4;
    for (int i = rgrp; i < NTOK; i += 8) {
        const int j0 = lane16, j1 = lane16 + 16, j2 = lane16 + 32;
        float a0 = 0.f, a1 = 0.f, a2 = 0.f, a3 = 0.f;
#pragma unroll
        for (int d = 0; d < DHEAD; d++) {
            const float qv = qs[i][d];
            a0 = fmaf(qv, ks[j0][d], a0);
            a1 = fmaf(qv, ks[j1][d], a1);
            a2 = fmaf(qv, ks[j2][d], a2);
            a3 = fmaf(qv, ks[48][d], a3);
        }
        ss[i][j0] = a0 + mrow[i * NTOK + j0];
        ss[i][j1] = a1 + mrow[i * NTOK + j1];
        ss[i][j2] = a2 + mrow[i * NTOK + j2];
        if (lane16 == 0) ss[i][48] = a3 + mrow[i * NTOK + 48];
    }
    __syncthreads();

    if (tid < NTOK) {
        float mx = -1e30f;
#pragma unroll
        for (int j = 0; j < NTOK; j++) mx = fmaxf(mx, ss[tid][j]);
        float sum = 0.f;
#pragma unroll
        for (int j = 0; j < NTOK; j++) {
            const float e = __expf(ss[tid][j] - mx);
            ss[tid][j] = e;
            sum += e;
        }
        const float inv = 1.0f / sum;
#pragma unroll
        for (int j = 0; j < NTOK; j++) ss[tid][j] *= inv;
    }
    __syncthreads();

    for (int e = tid; e < NTOK * DHEAD; e += 128) {
        const int i = e >> 5, d = e & 31;
        float acc = 0.f;
#pragma unroll
        for (int j = 0; j < NTOK; j++)
            acc = fmaf(ss[i][j], vs[j][d], acc);
        g_att[(size_t)(b * NTOK + i) * C_DIM + h * DHEAD + d] = acc;
    }
}

// ---------------------------------------------------------------------------
// Launch pipeline: QKV GEMM -> attention -> projection GEMM (+bias)
// ---------------------------------------------------------------------------
extern "C" void kernel_launch(void* const* d_in, const int* in_sizes, int n_in,
                              void* d_out, int out_size)
{
    const float* x      = (const float*)d_in[0];
    const float* mask   = (const float*)d_in[1];
    const float* w_qkv  = (const float*)d_in[2];
    const float* w_proj = (const float*)d_in[3];
    const float* b_proj = (const float*)d_in[4];
    float* out = (float*)d_out;

    float *qkvp, *attp;
    cudaGetSymbolAddress((void**)&qkvp, g_qkv);
    cudaGetSymbolAddress((void**)&attp, g_att);

    // QKV: [200704,192] @ [192,576]   (grid.x = N-blocks -> A-tile L2 reuse)
    mma_gemm<<<dim3(QKV_N / BN, M_TOTAL / BM), 256>>>(x, w_qkv, qkvp, nullptr, QKV_N);

    // Attention per (window, head)
    attn_kernel<<<B_WIN * NHEAD, 128>>>(mask);

    // Proj: [200704,192] @ [192,192] + bias
    mma_gemm<<<dim3(C_DIM / BN, M_TOTAL / BM), 256>>>(attp, w_proj, out, b_proj, C_DIM);
}

// round 9
// speedup vs baseline: 1.4853x; 1.1127x over previous
#include <cuda_runtime.h>
#include <cstdint>

// Problem constants (fixed by setup_inputs)
#define B_WIN   4096
#define NTOK    49
#define C_DIM   192
#define NHEAD   6
#define DHEAD   32
#define NWIN    64
#define M_TOTAL (B_WIN * NTOK)     // 200704 = 128 * 1568
#define QKV_N   576
#define KDIM    192

// Scratch (__device__ globals: allocation-guard-safe)
__device__ float g_qkv[(size_t)M_TOTAL * QKV_N];
__device__ float g_att[(size_t)M_TOTAL * C_DIM];

__device__ __forceinline__ uint32_t f2tf32(float f) {
    uint32_t r;
    asm("cvt.rna.tf32.f32 %0, %1;" : "=r"(r) : "f"(f));
    return r;
}

__device__ __forceinline__ void mma_tf32(float* c, const uint32_t* a, const uint32_t* b) {
    asm volatile(
        "mma.sync.aligned.m16n8k8.row.col.f32.tf32.tf32.f32 "
        "{%0,%1,%2,%3}, {%4,%5,%6,%7}, {%8,%9}, {%0,%1,%2,%3};"
        : "+f"(c[0]), "+f"(c[1]), "+f"(c[2]), "+f"(c[3])
        : "r"(a[0]), "r"(a[1]), "r"(a[2]), "r"(a[3]), "r"(b[0]), "r"(b[1]));
}

// ---------------------------------------------------------------------------
// tf32 mma.sync GEMM with fragment-permuted smem:
//   C[M_TOTAL, N] = A[M_TOTAL, 192] @ W[192, N]  (+bias)
// CTA 128x64, BK=32, 256 threads (8 warps, 4m x 2n, 32x32 per warp).
//
// A smem: 8 mb-blocks x 4 kb-blocks, each 16x8 tile = 128 words + 8 pad
//   (stride 136). Thread lane's 4 A-frag regs contiguous at lane*4 -> LDS.128.
// B smem: 8 nb-blocks x 4 kb-blocks, each 8x8 tile = 64 words + 8 pad
//   (stride 72). Thread lane's 2 B-frag regs contiguous at lane*2 -> LDS.64.
// ---------------------------------------------------------------------------
#define BM 128
#define BN 64
#define BK 32
#define ABLK 136
#define BBLK 72

__global__ __launch_bounds__(256)
void mma_gemm(const float* __restrict__ A, const float* __restrict__ W,
              float* __restrict__ C, const float* __restrict__ bias, int N)
{
    __shared__ uint32_t As[32 * ABLK];   // 17408 B
    __shared__ uint32_t Bs[32 * BBLK];   //  9216 B

    const int tid  = threadIdx.x;
    const int wid  = tid >> 5;
    const int lane = tid & 31;
    const int grp  = lane >> 2;
    const int quad = lane & 3;
    const int wm   = wid & 3;        // 4 m-warps
    const int wn   = wid >> 2;       // 2 n-warps
    const int m0   = blockIdx.y * BM;
    const int n0   = blockIdx.x * BN;

    float acc[2][4][4];
#pragma unroll
    for (int mt = 0; mt < 2; mt++)
#pragma unroll
        for (int nt = 0; nt < 4; nt++)
#pragma unroll
            for (int r = 0; r < 4; r++) acc[mt][nt][r] = 0.0f;

    for (int k0 = 0; k0 < KDIM; k0 += BK) {
        // ---- A tile: 128 rows x 32 k. f: m=f>>3 (coalesced rows), kq=f&7 ----
#pragma unroll
        for (int f = tid; f < BM * 8; f += 256) {
            const int m  = f >> 3;
            const int kq = f & 7;                 // float4 group along k
            const float4 v = *reinterpret_cast<const float4*>(
                A + (size_t)(m0 + m) * KDIM + k0 + kq * 4);
            const int mb   = m >> 4;
            const int g    = m & 7;
            const int rbit = (m >> 3) & 1;
            const int base = (mb * 4 + (kq >> 1)) * ABLK + rbit + ((kq & 1) << 1);
            As[base + g * 16 +  0] = f2tf32(v.x);
            As[base + g * 16 +  4] = f2tf32(v.y);
            As[base + g * 16 +  8] = f2tf32(v.z);
            As[base + g * 16 + 12] = f2tf32(v.w);
        }
        // ---- B tile: 32 k x 64 n. f: k=f&31 (conflict-free STS), nq=f>>5 ----
#pragma unroll
        for (int f = tid; f < BK * 16; f += 256) {
            const int k  = f & 31;
            const int nq = f >> 5;                // float4 group along n
            const float4 v = *reinterpret_cast<const float4*>(
                W + (size_t)(k0 + k) * N + n0 + nq * 4);
            const int kb  = k >> 3;
            const int kk  = k & 7;
            const int base = ((nq >> 1) * 4 + kb) * BBLK + ((nq & 1) << 5)
                             + ((kk & 3) << 1) + (kk >> 2);
            Bs[base +  0] = f2tf32(v.x);
            Bs[base +  8] = f2tf32(v.y);
            Bs[base + 16] = f2tf32(v.z);
            Bs[base + 24] = f2tf32(v.w);
        }
        __syncthreads();

#pragma unroll
        for (int ks = 0; ks < 4; ks++) {
            uint32_t a[2][4], b[4][2];
#pragma unroll
            for (int mt = 0; mt < 2; mt++) {
                const uint4 t = *reinterpret_cast<const uint4*>(
                    &As[((wm * 2 + mt) * 4 + ks) * ABLK + lane * 4]);
                a[mt][0] = t.x; a[mt][1] = t.y; a[mt][2] = t.z; a[mt][3] = t.w;
            }
#pragma unroll
            for (int nt = 0; nt < 4; nt++) {
                const uint2 t = *reinterpret_cast<const uint2*>(
                    &Bs[((wn * 4 + nt) * 4 + ks) * BBLK + lane * 2]);
                b[nt][0] = t.x; b[nt][1] = t.y;
            }
#pragma unroll
            for (int mt = 0; mt < 2; mt++)
#pragma unroll
                for (int nt = 0; nt < 4; nt++)
                    mma_tf32(acc[mt][nt], a[mt], b[nt]);
        }
        __syncthreads();
    }

    // Epilogue: each lane-quad writes a contiguous 32 B sector.
#pragma unroll
    for (int mt = 0; mt < 2; mt++) {
#pragma unroll
        for (int nt = 0; nt < 4; nt++) {
            const int row = m0 + wm * 32 + mt * 16 + grp;
            const int col = n0 + wn * 32 + nt * 8 + quad * 2;
            float b0 = 0.f, b1 = 0.f;
            if (bias) { b0 = bias[col]; b1 = bias[col + 1]; }
            float2 v0 = make_float2(acc[mt][nt][0] + b0, acc[mt][nt][1] + b1);
            float2 v1 = make_float2(acc[mt][nt][2] + b0, acc[mt][nt][3] + b1);
            *reinterpret_cast<float2*>(C + (size_t)row * N + col) = v0;
            *reinterpret_cast<float2*>(C + (size_t)(row + 8) * N + col) = v1;
        }
    }
}

// ---------------------------------------------------------------------------
// Attention v2: one block per (window, head), 128 threads.
// q,k transposed in smem ([d][i], pitch 52) -> S phase uses 4x4 register
// tiles with float4 loads. Softmax warp-per-row with shfl. PV uses 4x4
// (i,d) register tiles with float4 V loads.
// ---------------------------------------------------------------------------
#define QP 52      // pitch for transposed q/k (mult of 4)
#define VP 36      // pitch for v rows (mult of 4)
#define SP 53      // pitch for S (odd -> conflict-free column access)

__global__ __launch_bounds__(128)
void attn_kernel(const float* __restrict__ mask)
{
    __shared__ float qt[DHEAD][QP];       // q^T (scaled)
    __shared__ float kt[DHEAD][QP];       // k^T
    __shared__ float vs[NTOK][VP];        // v row-major
    __shared__ float ss[52][SP];          // S / P

    const int blk = blockIdx.x;
    const int b = blk / NHEAD;
    const int h = blk % NHEAD;
    const int tid = threadIdx.x;
    const int wid = tid >> 5;
    const int lane = tid & 31;
    const float scale = 0.17677669529663687f;

    const size_t base = (size_t)b * NTOK * QKV_N;
    const int qc = h * DHEAD;
    const int kc = C_DIM + h * DHEAD;
    const int vc = 2 * C_DIM + h * DHEAD;

    // ---- Load q (scaled, transposed), k (transposed), v (row-major) ----
    for (int f = tid; f < NTOK * 8; f += 128) {
        const int i = f >> 3, dq = (f & 7) * 4;
        const float* row = g_qkv + base + (size_t)i * QKV_N;
        const float4 q4 = *reinterpret_cast<const float4*>(row + qc + dq);
        const float4 k4 = *reinterpret_cast<const float4*>(row + kc + dq);
        const float4 v4 = *reinterpret_cast<const float4*>(row + vc + dq);
        qt[dq + 0][i] = q4.x * scale;
        qt[dq + 1][i] = q4.y * scale;
        qt[dq + 2][i] = q4.z * scale;
        qt[dq + 3][i] = q4.w * scale;
        kt[dq + 0][i] = k4.x;
        kt[dq + 1][i] = k4.y;
        kt[dq + 2][i] = k4.z;
        kt[dq + 3][i] = k4.w;
        *reinterpret_cast<float4*>(&vs[i][dq]) = v4;
    }
    __syncthreads();

    // ---- S = q k^T + mask : 13x13 tiles of 4x4 over padded 52x52 ----
    const float* mrow = mask + (size_t)(b & (NWIN - 1)) * NTOK * NTOK;
    for (int tt = tid; tt < 169; tt += 128) {
        const int i0 = (tt % 13) * 4;
        const int j0 = (tt / 13) * 4;
        float a[4][4];
#pragma unroll
        for (int ii = 0; ii < 4; ii++)
#pragma unroll
            for (int jj = 0; jj < 4; jj++) a[ii][jj] = 0.0f;
#pragma unroll
        for (int d = 0; d < DHEAD; d++) {
            const float4 qv = *reinterpret_cast<const float4*>(&qt[d][i0]);
            const float4 kv = *reinterpret_cast<const float4*>(&kt[d][j0]);
            const float qa[4] = {qv.x, qv.y, qv.z, qv.w};
            const float ka[4] = {kv.x, kv.y, kv.z, kv.w};
#pragma unroll
            for (int ii = 0; ii < 4; ii++)
#pragma unroll
                for (int jj = 0; jj < 4; jj++)
                    a[ii][jj] = fmaf(qa[ii], ka[jj], a[ii][jj]);
        }
#pragma unroll
        for (int ii = 0; ii < 4; ii++) {
            const int mi = (i0 + ii < NTOK) ? (i0 + ii) : (NTOK - 1);
#pragma unroll
            for (int jj = 0; jj < 4; jj++) {
                const int mj = (j0 + jj < NTOK) ? (j0 + jj) : (NTOK - 1);
                ss[i0 + ii][j0 + jj] = a[ii][jj] + mrow[mi * NTOK + mj];
            }
        }
    }
    __syncthreads();

    // ---- Softmax: warp per row, shfl reductions ----
    for (int r = wid; r < NTOK; r += 4) {
        const float x0 = ss[r][lane];
        const float x1 = (lane < NTOK - 32) ? ss[r][lane + 32] : -1e30f;
        float mx = fmaxf(x0, x1);
#pragma unroll
        for (int off = 16; off > 0; off >>= 1)
            mx = fmaxf(mx, __shfl_xor_sync(0xFFFFFFFFu, mx, off));
        const float e0 = __expf(x0 - mx);
        const float e1 = (lane < NTOK - 32) ? __expf(x1 - mx) : 0.0f;
        float s = e0 + e1;
#pragma unroll
        for (int off = 16; off > 0; off >>= 1)
            s += __shfl_xor_sync(0xFFFFFFFFu, s, off);
        const float inv = 1.0f / s;
        ss[r][lane] = e0 * inv;
        if (lane < NTOK - 32) ss[r][lane + 32] = e1 * inv;
    }
    __syncthreads();

    // ---- O = P V : 13 i-tiles x 8 d-tiles of 4x4 ----
    if (tid < 104) {
        const int i0 = (tid % 13) * 4;
        const int d0 = (tid / 13) * 4;
        float a[4][4];
#pragma unroll
        for (int ii = 0; ii < 4; ii++)
#pragma unroll
            for (int dd = 0; dd < 4; dd++) a[ii][dd] = 0.0f;
        for (int j = 0; j < NTOK; j++) {
            const float4 vv = *reinterpret_cast<const float4*>(&vs[j][d0]);
            const float va[4] = {vv.x, vv.y, vv.z, vv.w};
            const float p0 = ss[i0 + 0][j];
            const float p1 = ss[i0 + 1][j];
            const float p2 = ss[i0 + 2][j];
            const float p3 = ss[i0 + 3][j];
#pragma unroll
            for (int dd = 0; dd < 4; dd++) {
                a[0][dd] = fmaf(p0, va[dd], a[0][dd]);
                a[1][dd] = fmaf(p1, va[dd], a[1][dd]);
                a[2][dd] = fmaf(p2, va[dd], a[2][dd]);
                a[3][dd] = fmaf(p3, va[dd], a[3][dd]);
            }
        }
#pragma unroll
        for (int ii = 0; ii < 4; ii++) {
            const int i = i0 + ii;
            if (i < NTOK) {
                float4 o = make_float4(a[ii][0], a[ii][1], a[ii][2], a[ii][3]);
                *reinterpret_cast<float4*>(
                    g_att + (size_t)(b * NTOK + i) * C_DIM + h * DHEAD + d0) = o;
            }
        }
    }
}

// ---------------------------------------------------------------------------
// Launch pipeline: QKV GEMM -> attention -> projection GEMM (+bias)
// ---------------------------------------------------------------------------
extern "C" void kernel_launch(void* const* d_in, const int* in_sizes, int n_in,
                              void* d_out, int out_size)
{
    const float* x      = (const float*)d_in[0];
    const float* mask   = (const float*)d_in[1];
    const float* w_qkv  = (const float*)d_in[2];
    const float* w_proj = (const float*)d_in[3];
    const float* b_proj = (const float*)d_in[4];
    float* out = (float*)d_out;

    float *qkvp, *attp;
    cudaGetSymbolAddress((void**)&qkvp, g_qkv);
    cudaGetSymbolAddress((void**)&attp, g_att);

    // QKV: [200704,192] @ [192,576]   (grid.x = N-blocks -> A-tile L2 reuse)
    mma_gemm<<<dim3(QKV_N / BN, M_TOTAL / BM), 256>>>(x, w_qkv, qkvp, nullptr, QKV_N);

    // Attention per (window, head)
    attn_kernel<<<B_WIN * NHEAD, 128>>>(mask);

    // Proj: [200704,192] @ [192,192] + bias
    mma_gemm<<<dim3(C_DIM / BN, M_TOTAL / BM), 256>>>(attp, w_proj, out, b_proj, C_DIM);
}

// round 10
// speedup vs baseline: 2.0222x; 1.3614x over previous
#include <cuda_runtime.h>
#include <cuda_fp16.h>
#include <cstdint>

// Problem constants (fixed by setup_inputs)
#define B_WIN   4096
#define NTOK    49
#define C_DIM   192
#define NHEAD   6
#define DHEAD   32
#define NWIN    64
#define M_TOTAL (B_WIN * NTOK)     // 200704 = 128 * 1568
#define QKV_N   576
#define KDIM    192

// Scratch (__device__ globals: allocation-guard-safe)
__device__ float g_qkv[(size_t)M_TOTAL * QKV_N];
__device__ float g_att[(size_t)M_TOTAL * C_DIM];

// pack two f32 -> f16x2 (lo = first arg)
__device__ __forceinline__ uint32_t packh2(float lo, float hi) {
    uint32_t r;
    asm("cvt.rn.f16x2.f32 %0, %1, %2;" : "=r"(r) : "f"(hi), "f"(lo));
    return r;
}

__device__ __forceinline__ void mma_f16(float* c, const uint32_t* a, const uint32_t* b) {
    asm volatile(
        "mma.sync.aligned.m16n8k16.row.col.f32.f16.f16.f32 "
        "{%0,%1,%2,%3}, {%4,%5,%6,%7}, {%8,%9}, {%0,%1,%2,%3};"
        : "+f"(c[0]), "+f"(c[1]), "+f"(c[2]), "+f"(c[3])
        : "r"(a[0]), "r"(a[1]), "r"(a[2]), "r"(a[3]), "r"(b[0]), "r"(b[1]));
}

// ---------------------------------------------------------------------------
// fp16 mma.sync GEMM:  C[M_TOTAL, N] = A[M_TOTAL, 192] @ W[192, N]  (+bias)
// CTA 128x64, BK=32, 256 threads (8 warps, 4m x 2n, warp tile 32x32).
//
// A smem: 16 tiles (mb 0..7 x ks 0..1) of m16 x kp8 half2-words, pitch 132.
//   word_in_tile = (grp*4+quad)*4 + mbit + 2*khig  -> thread frag = LDS.128.
//   Writer row map bit-mixed so every warp's STS.32 covers all 32 banks.
// B smem: [kp 0..15][n 0..63] half2-words, pitch 72 (== 8 mod 32).
//   Writer: 1 conflict-free STS.128/thread; frag reads: conflict-free LDS.32.
// ---------------------------------------------------------------------------
#define BM 128
#define BN 64
#define BK 32
#define ATILE 132     // words per A tile (128 + 4 pad); 132 % 32 == 4
#define BPITCH 72     // words per kp-row of B (64 + 8 pad); 72 % 32 == 8

__global__ __launch_bounds__(256)
void mma_gemm(const float* __restrict__ A, const float* __restrict__ W,
              float* __restrict__ C, const float* __restrict__ bias, int N)
{
    __shared__ __align__(16) uint32_t As[16 * ATILE];   // 8448 B
    __shared__ __align__(16) uint32_t Bs[16 * BPITCH];  // 4608 B

    const int tid  = threadIdx.x;
    const int wid  = tid >> 5;
    const int lane = tid & 31;
    const int grp  = lane >> 2;
    const int quad = lane & 3;
    const int wm   = wid & 3;        // 4 m-warps (32 rows each)
    const int wn   = wid >> 2;       // 2 n-warps (32 cols each)
    const int m0   = blockIdx.y * BM;
    const int n0   = blockIdx.x * BN;

    float acc[2][4][4];
#pragma unroll
    for (int mt = 0; mt < 2; mt++)
#pragma unroll
        for (int nt = 0; nt < 4; nt++)
#pragma unroll
            for (int r = 0; r < 4; r++) acc[mt][nt][r] = 0.0f;

    for (int k0 = 0; k0 < KDIM; k0 += BK) {
        // ---- A tile: 128 rows x 32 k (1024 float4 tasks, 4/thread) ----
#pragma unroll
        for (int f = tid; f < BM * 8; f += 256) {
            const int mm = f >> 3;
            const int kq = f & 7;
            // bit-mixed row: warp's 4 tasks span both mbit halves
            const int m = ((mm & 1) << 3) | ((mm >> 1) & 7) | (mm & 0x70);
            const float4 v = *reinterpret_cast<const float4*>(
                A + (size_t)(m0 + m) * KDIM + k0 + kq * 4);
            const uint32_t h0 = packh2(v.x, v.y);   // kp = 2kq
            const uint32_t h1 = packh2(v.z, v.w);   // kp = 2kq+1
            const int g    = m & 7;
            const int mbit = (m >> 3) & 1;
            const int mb   = m >> 4;
            const int kp   = kq * 2;
            const int ks   = kp >> 3;
            const int kpl  = kp & 7;
            const int qd   = kpl & 3;
            const int kh   = kpl >> 2;
            const int w = (mb * 2 + ks) * ATILE + (g * 4 + qd) * 4 + mbit + 2 * kh;
            As[w]     = h0;
            As[w + 4] = h1;   // quad+1 -> +4 words
        }
        // ---- B tile: 32 k x 64 n (256 tasks, 1/thread) ----
        {
            const int n4 = tid & 15;         // n = n4*4
            const int kp = tid >> 4;         // kp = k/2, 0..15
            const float* r0 = W + (size_t)(k0 + 2 * kp) * N + n0 + n4 * 4;
            const float4 v0 = *reinterpret_cast<const float4*>(r0);
            const float4 v1 = *reinterpret_cast<const float4*>(r0 + N);
            uint4 h;
            h.x = packh2(v0.x, v1.x);
            h.y = packh2(v0.y, v1.y);
            h.z = packh2(v0.z, v1.z);
            h.w = packh2(v0.w, v1.w);
            *reinterpret_cast<uint4*>(&Bs[kp * BPITCH + n4 * 4]) = h;
        }
        __syncthreads();

#pragma unroll
        for (int ks = 0; ks < 2; ks++) {     // two k16 steps per BK=32
            uint32_t a[2][4], b[4][2];
#pragma unroll
            for (int mt = 0; mt < 2; mt++) {
                const uint4 t = *reinterpret_cast<const uint4*>(
                    &As[((wm * 2 + mt) * 2 + ks) * ATILE + lane * 4]);
                a[mt][0] = t.x; a[mt][1] = t.y; a[mt][2] = t.z; a[mt][3] = t.w;
            }
#pragma unroll
            for (int nt = 0; nt < 4; nt++) {
                const int n = wn * 32 + nt * 8 + grp;
                b[nt][0] = Bs[(ks * 8 + quad    ) * BPITCH + n];
                b[nt][1] = Bs[(ks * 8 + quad + 4) * BPITCH + n];
            }
#pragma unroll
            for (int mt = 0; mt < 2; mt++)
#pragma unroll
                for (int nt = 0; nt < 4; nt++)
                    mma_f16(acc[mt][nt], a[mt], b[nt]);
        }
        __syncthreads();
    }

    // Epilogue: each lane-quad writes a contiguous 32 B sector.
#pragma unroll
    for (int mt = 0; mt < 2; mt++) {
#pragma unroll
        for (int nt = 0; nt < 4; nt++) {
            const int row = m0 + wm * 32 + mt * 16 + grp;
            const int col = n0 + wn * 32 + nt * 8 + quad * 2;
            float b0 = 0.f, b1 = 0.f;
            if (bias) { b0 = bias[col]; b1 = bias[col + 1]; }
            float2 v0 = make_float2(acc[mt][nt][0] + b0, acc[mt][nt][1] + b1);
            float2 v1 = make_float2(acc[mt][nt][2] + b0, acc[mt][nt][3] + b1);
            *reinterpret_cast<float2*>(C + (size_t)row * N + col) = v0;
            *reinterpret_cast<float2*>(C + (size_t)(row + 8) * N + col) = v1;
        }
    }
}

// ---------------------------------------------------------------------------
// Attention v2 (unchanged from R9): one block per (window, head), 128 thr.
// ---------------------------------------------------------------------------
#define QP 52
#define VP 36
#define SP 53

__global__ __launch_bounds__(128)
void attn_kernel(const float* __restrict__ mask)
{
    __shared__ float qt[DHEAD][QP];
    __shared__ float kt[DHEAD][QP];
    __shared__ float vs[NTOK][VP];
    __shared__ float ss[52][SP];

    const int blk = blockIdx.x;
    const int b = blk / NHEAD;
    const int h = blk % NHEAD;
    const int tid = threadIdx.x;
    const int wid = tid >> 5;
    const int lane = tid & 31;
    const float scale = 0.17677669529663687f;

    const size_t base = (size_t)b * NTOK * QKV_N;
    const int qc = h * DHEAD;
    const int kc = C_DIM + h * DHEAD;
    const int vc = 2 * C_DIM + h * DHEAD;

    for (int f = tid; f < NTOK * 8; f += 128) {
        const int i = f >> 3, dq = (f & 7) * 4;
        const float* row = g_qkv + base + (size_t)i * QKV_N;
        const float4 q4 = *reinterpret_cast<const float4*>(row + qc + dq);
        const float4 k4 = *reinterpret_cast<const float4*>(row + kc + dq);
        const float4 v4 = *reinterpret_cast<const float4*>(row + vc + dq);
        qt[dq + 0][i] = q4.x * scale;
        qt[dq + 1][i] = q4.y * scale;
        qt[dq + 2][i] = q4.z * scale;
        qt[dq + 3][i] = q4.w * scale;
        kt[dq + 0][i] = k4.x;
        kt[dq + 1][i] = k4.y;
        kt[dq + 2][i] = k4.z;
        kt[dq + 3][i] = k4.w;
        *reinterpret_cast<float4*>(&vs[i][dq]) = v4;
    }
    __syncthreads();

    const float* mrow = mask + (size_t)(b & (NWIN - 1)) * NTOK * NTOK;
    for (int tt = tid; tt < 169; tt += 128) {
        const int i0 = (tt % 13) * 4;
        const int j0 = (tt / 13) * 4;
        float a[4][4];
#pragma unroll
        for (int ii = 0; ii < 4; ii++)
#pragma unroll
            for (int jj = 0; jj < 4; jj++) a[ii][jj] = 0.0f;
#pragma unroll
        for (int d = 0; d < DHEAD; d++) {
            const float4 qv = *reinterpret_cast<const float4*>(&qt[d][i0]);
            const float4 kv = *reinterpret_cast<const float4*>(&kt[d][j0]);
            const float qa[4] = {qv.x, qv.y, qv.z, qv.w};
            const float ka[4] = {kv.x, kv.y, kv.z, kv.w};
#pragma unroll
            for (int ii = 0; ii < 4; ii++)
#pragma unroll
                for (int jj = 0; jj < 4; jj++)
                    a[ii][jj] = fmaf(qa[ii], ka[jj], a[ii][jj]);
        }
#pragma unroll
        for (int ii = 0; ii < 4; ii++) {
            const int mi = (i0 + ii < NTOK) ? (i0 + ii) : (NTOK - 1);
#pragma unroll
            for (int jj = 0; jj < 4; jj++) {
                const int mj = (j0 + jj < NTOK) ? (j0 + jj) : (NTOK - 1);
                ss[i0 + ii][j0 + jj] = a[ii][jj] + mrow[mi * NTOK + mj];
            }
        }
    }
    __syncthreads();

    for (int r = wid; r < NTOK; r += 4) {
        const float x0 = ss[r][lane];
        const float x1 = (lane < NTOK - 32) ? ss[r][lane + 32] : -1e30f;
        float mx = fmaxf(x0, x1);
#pragma unroll
        for (int off = 16; off > 0; off >>= 1)
            mx = fmaxf(mx, __shfl_xor_sync(0xFFFFFFFFu, mx, off));
        const float e0 = __expf(x0 - mx);
        const float e1 = (lane < NTOK - 32) ? __expf(x1 - mx) : 0.0f;
        float s = e0 + e1;
#pragma unroll
        for (int off = 16; off > 0; off >>= 1)
            s += __shfl_xor_sync(0xFFFFFFFFu, s, off);
        const float inv = 1.0f / s;
        ss[r][lane] = e0 * inv;
        if (lane < NTOK - 32) ss[r][lane + 32] = e1 * inv;
    }
    __syncthreads();

    if (tid < 104) {
        const int i0 = (tid % 13) * 4;
        const int d0 = (tid / 13) * 4;
        float a[4][4];
#pragma unroll
        for (int ii = 0; ii < 4; ii++)
#pragma unroll
            for (int dd = 0; dd < 4; dd++) a[ii][dd] = 0.0f;
        for (int j = 0; j < NTOK; j++) {
            const float4 vv = *reinterpret_cast<const float4*>(&vs[j][d0]);
            const float va[4] = {vv.x, vv.y, vv.z, vv.w};
            const float p0 = ss[i0 + 0][j];
            const float p1 = ss[i0 + 1][j];
            const float p2 = ss[i0 + 2][j];
            const float p3 = ss[i0 + 3][j];
#pragma unroll
            for (int dd = 0; dd < 4; dd++) {
                a[0][dd] = fmaf(p0, va[dd], a[0][dd]);
                a[1][dd] = fmaf(p1, va[dd], a[1][dd]);
                a[2][dd] = fmaf(p2, va[dd], a[2][dd]);
                a[3][dd] = fmaf(p3, va[dd], a[3][dd]);
            }
        }
#pragma unroll
        for (int ii = 0; ii < 4; ii++) {
            const int i = i0 + ii;
            if (i < NTOK) {
                float4 o = make_float4(a[ii][0], a[ii][1], a[ii][2], a[ii][3]);
                *reinterpret_cast<float4*>(
                    g_att + (size_t)(b * NTOK + i) * C_DIM + h * DHEAD + d0) = o;
            }
        }
    }
}

// ---------------------------------------------------------------------------
// Launch pipeline: QKV GEMM -> attention -> projection GEMM (+bias)
// ---------------------------------------------------------------------------
extern "C" void kernel_launch(void* const* d_in, const int* in_sizes, int n_in,
                              void* d_out, int out_size)
{
    const float* x      = (const float*)d_in[0];
    const float* mask   = (const float*)d_in[1];
    const float* w_qkv  = (const float*)d_in[2];
    const float* w_proj = (const float*)d_in[3];
    const float* b_proj = (const float*)d_in[4];
    float* out = (float*)d_out;

    float *qkvp, *attp;
    cudaGetSymbolAddress((void**)&qkvp, g_qkv);
    cudaGetSymbolAddress((void**)&attp, g_att);

    // QKV: [200704,192] @ [192,576]   (grid.x = N-blocks -> A-tile L2 reuse)
    mma_gemm<<<dim3(QKV_N / BN, M_TOTAL / BM), 256>>>(x, w_qkv, qkvp, nullptr, QKV_N);

    // Attention per (window, head)
    attn_kernel<<<B_WIN * NHEAD, 128>>>(mask);

    // Proj: [200704,192] @ [192,192] + bias
    mma_gemm<<<dim3(C_DIM / BN, M_TOTAL / BM), 256>>>(attp, w_proj, out, b_proj, C_DIM);
}

// round 12
// speedup vs baseline: 2.8446x; 1.4067x over previous
#include <cuda_runtime.h>
#include <cuda_fp16.h>
#include <cstdint>

// Problem constants (fixed by setup_inputs)
#define B_WIN   4096
#define NTOK    49
#define C_DIM   192
#define NHEAD   6
#define DHEAD   32
#define NWIN    64
#define M_TOTAL (B_WIN * NTOK)     // 200704 = 128 * 1568
#define QKV_N   576
#define KDIM    192

// Scratch (__device__ globals: allocation-guard-safe)
__device__ unsigned short g_qkv_h[(size_t)M_TOTAL * QKV_N];  // fp16 qkv
__device__ float g_att[(size_t)M_TOTAL * C_DIM];

// pack two f32 -> f16x2 (first arg = low half)
__device__ __forceinline__ uint32_t packh2(float lo, float hi) {
    uint32_t r;
    asm("cvt.rn.f16x2.f32 %0, %1, %2;" : "=r"(r) : "f"(hi), "f"(lo));
    return r;
}

__device__ __forceinline__ void mma_f16(float* c, const uint32_t* a, const uint32_t* b) {
    asm volatile(
        "mma.sync.aligned.m16n8k16.row.col.f32.f16.f16.f32 "
        "{%0,%1,%2,%3}, {%4,%5,%6,%7}, {%8,%9}, {%0,%1,%2,%3};"
        : "+f"(c[0]), "+f"(c[1]), "+f"(c[2]), "+f"(c[3])
        : "r"(a[0]), "r"(a[1]), "r"(a[2]), "r"(a[3]), "r"(b[0]), "r"(b[1]));
}

// Epilogue store helpers (overloaded on output type)
__device__ __forceinline__ void store2(float* C, size_t idx, float a, float b) {
    *reinterpret_cast<float2*>(C + idx) = make_float2(a, b);
}
__device__ __forceinline__ void store2(__half* C, size_t idx, float a, float b) {
    *reinterpret_cast<uint32_t*>(C + idx) = packh2(a, b);
}

// ---------------------------------------------------------------------------
// fp16 mma.sync GEMM:  C[M_TOTAL, N] = A[M_TOTAL, 192] @ W[192, N]  (+bias)
// CTA 128x64, BK=32, 256 threads (8 warps, 4m x 2n, warp tile 32x32).
// Layouts validated in R10; output type templated (half for QKV, float proj).
// ---------------------------------------------------------------------------
#define BM 128
#define BN 64
#define BK 32
#define ATILE 132
#define BPITCH 72

template<typename TOUT>
__global__ __launch_bounds__(256)
void mma_gemm(const float* __restrict__ A, const float* __restrict__ W,
              TOUT* __restrict__ C, const float* __restrict__ bias, int N)
{
    __shared__ __align__(16) uint32_t As[16 * ATILE];
    __shared__ __align__(16) uint32_t Bs[16 * BPITCH];

    const int tid  = threadIdx.x;
    const int wid  = tid >> 5;
    const int lane = tid & 31;
    const int grp  = lane >> 2;
    const int quad = lane & 3;
    const int wm   = wid & 3;
    const int wn   = wid >> 2;
    const int m0   = blockIdx.y * BM;
    const int n0   = blockIdx.x * BN;

    float acc[2][4][4];
#pragma unroll
    for (int mt = 0; mt < 2; mt++)
#pragma unroll
        for (int nt = 0; nt < 4; nt++)
#pragma unroll
            for (int r = 0; r < 4; r++) acc[mt][nt][r] = 0.0f;

    for (int k0 = 0; k0 < KDIM; k0 += BK) {
#pragma unroll
        for (int f = tid; f < BM * 8; f += 256) {
            const int mm = f >> 3;
            const int kq = f & 7;
            const int m = ((mm & 1) << 3) | ((mm >> 1) & 7) | (mm & 0x70);
            const float4 v = *reinterpret_cast<const float4*>(
                A + (size_t)(m0 + m) * KDIM + k0 + kq * 4);
            const uint32_t h0 = packh2(v.x, v.y);
            const uint32_t h1 = packh2(v.z, v.w);
            const int g    = m & 7;
            const int mbit = (m >> 3) & 1;
            const int mb   = m >> 4;
            const int kp   = kq * 2;
            const int ks   = kp >> 3;
            const int kpl  = kp & 7;
            const int qd   = kpl & 3;
            const int kh   = kpl >> 2;
            const int w = (mb * 2 + ks) * ATILE + (g * 4 + qd) * 4 + mbit + 2 * kh;
            As[w]     = h0;
            As[w + 4] = h1;
        }
        {
            const int n4 = tid & 15;
            const int kp = tid >> 4;
            const float* r0 = W + (size_t)(k0 + 2 * kp) * N + n0 + n4 * 4;
            const float4 v0 = *reinterpret_cast<const float4*>(r0);
            const float4 v1 = *reinterpret_cast<const float4*>(r0 + N);
            uint4 h;
            h.x = packh2(v0.x, v1.x);
            h.y = packh2(v0.y, v1.y);
            h.z = packh2(v0.z, v1.z);
            h.w = packh2(v0.w, v1.w);
            *reinterpret_cast<uint4*>(&Bs[kp * BPITCH + n4 * 4]) = h;
        }
        __syncthreads();

#pragma unroll
        for (int ks = 0; ks < 2; ks++) {
            uint32_t a[2][4], b[4][2];
#pragma unroll
            for (int mt = 0; mt < 2; mt++) {
                const uint4 t = *reinterpret_cast<const uint4*>(
                    &As[((wm * 2 + mt) * 2 + ks) * ATILE + lane * 4]);
                a[mt][0] = t.x; a[mt][1] = t.y; a[mt][2] = t.z; a[mt][3] = t.w;
            }
#pragma unroll
            for (int nt = 0; nt < 4; nt++) {
                const int n = wn * 32 + nt * 8 + grp;
                b[nt][0] = Bs[(ks * 8 + quad    ) * BPITCH + n];
                b[nt][1] = Bs[(ks * 8 + quad + 4) * BPITCH + n];
            }
#pragma unroll
            for (int mt = 0; mt < 2; mt++)
#pragma unroll
                for (int nt = 0; nt < 4; nt++)
                    mma_f16(acc[mt][nt], a[mt], b[nt]);
        }
        __syncthreads();
    }

#pragma unroll
    for (int mt = 0; mt < 2; mt++) {
#pragma unroll
        for (int nt = 0; nt < 4; nt++) {
            const int row = m0 + wm * 32 + mt * 16 + grp;
            const int col = n0 + wn * 32 + nt * 8 + quad * 2;
            float b0 = 0.f, b1 = 0.f;
            if (bias) { b0 = bias[col]; b1 = bias[col + 1]; }
            store2(C, (size_t)row * N + col,
                   acc[mt][nt][0] + b0, acc[mt][nt][1] + b1);
            store2(C, (size_t)(row + 8) * N + col,
                   acc[mt][nt][2] + b0, acc[mt][nt][3] + b1);
        }
    }
}

// ---------------------------------------------------------------------------
// Tensor-core attention: one block per window (4096 blocks), 384 threads =
// 6 heads x 2 warps. Warp owns 32 rows (m-tiles), S over 64 padded cols,
// fragment-resident softmax, in-register P repack, PV mma.
//
// smem (words): mask[49x50] @0 (2452) | per head (3712):
//   Qs [row][kp] pitch 20, Ks same @+1280, Vt [d][jp] pitch 36 @+2560
// ---------------------------------------------------------------------------
#define MSW   2452
#define HEADW 3712
#define ATT_SMEM_BYTES ((MSW + 6 * HEADW) * 4)   // 98896

__global__ __launch_bounds__(384)
void attn_kernel(const float* __restrict__ mask)
{
    extern __shared__ uint32_t smw[];
    float* ms = reinterpret_cast<float*>(smw);
    const int b = blockIdx.x;
    const int tid = threadIdx.x;
    const __half* qkv = reinterpret_cast<const __half*>(g_qkv_h);

    // ---- mask: 49x49 -> pitch 50 ----
    const float* msrc = mask + (size_t)(b & (NWIN - 1)) * NTOK * NTOK;
    for (int f = tid; f < NTOK * NTOK; f += 384) {
        const int i = f / 49;
        ms[i * 50 + (f - i * 49)] = msrc[f];
    }
    // ---- Q/K: half2 copies into [row][kp] pitch-20.
    //      FIX(R11): 4 uint4 chunks per 32-half row (c=0..3), 2352 tasks. ----
    for (int f = tid; f < 2352; f += 384) {
        const int h = f / 392, rem = f % 392;
        const int sel = rem / 196, r2 = rem % 196;
        const int i = r2 >> 2, c = r2 & 3;
        const uint4 v = *reinterpret_cast<const uint4*>(
            qkv + ((size_t)b * NTOK + i) * QKV_N + sel * C_DIM + h * 32 + c * 8);
        *reinterpret_cast<uint4*>(smw + MSW + h * HEADW + sel * 1280 + i * 20 + c * 4) = v;
    }
    // ---- V transpose into [d][jp] pitch-36 (pads zeroed via predication) ----
    for (int f = tid; f < 768; f += 384) {
        const int h = f / 128, rem = f % 128;
        const int jp = rem >> 2, dq = rem & 3;
        uint4 lo4 = make_uint4(0, 0, 0, 0), hi4 = make_uint4(0, 0, 0, 0);
        const __half* basep = qkv + ((size_t)b * NTOK + 2 * jp) * QKV_N
                              + 2 * C_DIM + h * 32 + dq * 8;
        if (2 * jp     < NTOK) lo4 = *reinterpret_cast<const uint4*>(basep);
        if (2 * jp + 1 < NTOK) hi4 = *reinterpret_cast<const uint4*>(basep + QKV_N);
        const __half* lo = reinterpret_cast<const __half*>(&lo4);
        const __half* hi = reinterpret_cast<const __half*>(&hi4);
        uint32_t* Vh = smw + MSW + h * HEADW + 2560;
#pragma unroll
        for (int t = 0; t < 8; t++) {
            __half2 hv = __halves2half2(lo[t], hi[t]);
            Vh[(dq * 8 + t) * 36 + jp] = *reinterpret_cast<uint32_t*>(&hv);
        }
    }
    __syncthreads();

    const int wid = tid >> 5, lane = tid & 31;
    const int g = lane >> 2, q = lane & 3;
    const int h = wid >> 1;
    const int rowbase = (wid & 1) * 32;
    const uint32_t* Qs = smw + MSW + h * HEADW;
    const uint32_t* Ks = Qs + 1280;
    const uint32_t* Vt = Qs + 2560;

    // ---- S = Q K^T : 2 m-tiles x 8 n-tiles ----
    float s[2][8][4] = {};
#pragma unroll
    for (int ks = 0; ks < 2; ks++) {
        uint32_t a[2][4];
#pragma unroll
        for (int mtl = 0; mtl < 2; mtl++) {
            const int r = rowbase + mtl * 16 + g;
            a[mtl][0] = Qs[r * 20 + 8 * ks + q];
            a[mtl][1] = Qs[(r + 8) * 20 + 8 * ks + q];
            a[mtl][2] = Qs[r * 20 + 8 * ks + q + 4];
            a[mtl][3] = Qs[(r + 8) * 20 + 8 * ks + q + 4];
        }
#pragma unroll
        for (int nt = 0; nt < 8; nt++) {
            uint32_t bb[2];
            bb[0] = Ks[(8 * nt + g) * 20 + 8 * ks + q];
            bb[1] = Ks[(8 * nt + g) * 20 + 8 * ks + q + 4];
            mma_f16(s[0][nt], a[0], bb);
            mma_f16(s[1][nt], a[1], bb);
        }
    }

    // ---- scale + mask (invalid cols -> -1e30) ----
    const float scale = 0.17677669529663687f;
#pragma unroll
    for (int mtl = 0; mtl < 2; mtl++) {
        const int r1 = rowbase + mtl * 16 + g;
        const int rc1 = min(r1, 48) * 50, rc2 = min(r1 + 8, 48) * 50;
#pragma unroll
        for (int nt = 0; nt < 8; nt++) {
            const int j0 = 8 * nt + 2 * q, j1 = j0 + 1;
            if (j0 < NTOK) {
                s[mtl][nt][0] = fmaf(s[mtl][nt][0], scale, ms[rc1 + j0]);
                s[mtl][nt][2] = fmaf(s[mtl][nt][2], scale, ms[rc2 + j0]);
            } else { s[mtl][nt][0] = -1e30f; s[mtl][nt][2] = -1e30f; }
            if (j1 < NTOK) {
                s[mtl][nt][1] = fmaf(s[mtl][nt][1], scale, ms[rc1 + j1]);
                s[mtl][nt][3] = fmaf(s[mtl][nt][3], scale, ms[rc2 + j1]);
            } else { s[mtl][nt][1] = -1e30f; s[mtl][nt][3] = -1e30f; }
        }
    }

    // ---- fragment softmax: rows owned by lane quads, shfl xor 1,2 ----
#pragma unroll
    for (int mtl = 0; mtl < 2; mtl++) {
        float mxA = -1e30f, mxB = -1e30f;
#pragma unroll
        for (int nt = 0; nt < 8; nt++) {
            mxA = fmaxf(mxA, fmaxf(s[mtl][nt][0], s[mtl][nt][1]));
            mxB = fmaxf(mxB, fmaxf(s[mtl][nt][2], s[mtl][nt][3]));
        }
        mxA = fmaxf(mxA, __shfl_xor_sync(0xFFFFFFFFu, mxA, 1));
        mxA = fmaxf(mxA, __shfl_xor_sync(0xFFFFFFFFu, mxA, 2));
        mxB = fmaxf(mxB, __shfl_xor_sync(0xFFFFFFFFu, mxB, 1));
        mxB = fmaxf(mxB, __shfl_xor_sync(0xFFFFFFFFu, mxB, 2));
        float sA = 0.f, sB = 0.f;
#pragma unroll
        for (int nt = 0; nt < 8; nt++) {
            s[mtl][nt][0] = __expf(s[mtl][nt][0] - mxA); sA += s[mtl][nt][0];
            s[mtl][nt][1] = __expf(s[mtl][nt][1] - mxA); sA += s[mtl][nt][1];
            s[mtl][nt][2] = __expf(s[mtl][nt][2] - mxB); sB += s[mtl][nt][2];
            s[mtl][nt][3] = __expf(s[mtl][nt][3] - mxB); sB += s[mtl][nt][3];
        }
        sA += __shfl_xor_sync(0xFFFFFFFFu, sA, 1);
        sA += __shfl_xor_sync(0xFFFFFFFFu, sA, 2);
        sB += __shfl_xor_sync(0xFFFFFFFFu, sB, 1);
        sB += __shfl_xor_sync(0xFFFFFFFFu, sB, 2);
        const float invA = 1.0f / sA, invB = 1.0f / sB;
#pragma unroll
        for (int nt = 0; nt < 8; nt++) {
            s[mtl][nt][0] *= invA; s[mtl][nt][1] *= invA;
            s[mtl][nt][2] *= invB; s[mtl][nt][3] *= invB;
        }
    }

    // ---- O = P V : repack S C-frags as PV A-frags (pure register op) ----
    float o[2][4][4] = {};
#pragma unroll
    for (int ks = 0; ks < 4; ks++) {
        uint32_t pa[2][4];
#pragma unroll
        for (int mtl = 0; mtl < 2; mtl++) {
            pa[mtl][0] = packh2(s[mtl][2 * ks][0],     s[mtl][2 * ks][1]);
            pa[mtl][1] = packh2(s[mtl][2 * ks][2],     s[mtl][2 * ks][3]);
            pa[mtl][2] = packh2(s[mtl][2 * ks + 1][0], s[mtl][2 * ks + 1][1]);
            pa[mtl][3] = packh2(s[mtl][2 * ks + 1][2], s[mtl][2 * ks + 1][3]);
        }
#pragma unroll
        for (int nt2 = 0; nt2 < 4; nt2++) {
            uint32_t bb[2];
            bb[0] = Vt[(8 * nt2 + g) * 36 + 8 * ks + q];
            bb[1] = Vt[(8 * nt2 + g) * 36 + 8 * ks + q + 4];
            mma_f16(o[0][nt2], pa[0], bb);
            mma_f16(o[1][nt2], pa[1], bb);
        }
    }

    // ---- store valid rows to g_att (fp32) ----
#pragma unroll
    for (int mtl = 0; mtl < 2; mtl++) {
        const int r1 = rowbase + mtl * 16 + g, r2 = r1 + 8;
#pragma unroll
        for (int nt2 = 0; nt2 < 4; nt2++) {
            const int col = h * 32 + 8 * nt2 + 2 * q;
            if (r1 < NTOK)
                *reinterpret_cast<float2*>(
                    g_att + ((size_t)b * NTOK + r1) * C_DIM + col) =
                    make_float2(o[mtl][nt2][0], o[mtl][nt2][1]);
            if (r2 < NTOK)
                *reinterpret_cast<float2*>(
                    g_att + ((size_t)b * NTOK + r2) * C_DIM + col) =
                    make_float2(o[mtl][nt2][2], o[mtl][nt2][3]);
        }
    }
}

// ---------------------------------------------------------------------------
// Launch pipeline
// ---------------------------------------------------------------------------
extern "C" void kernel_launch(void* const* d_in, const int* in_sizes, int n_in,
                              void* d_out, int out_size)
{
    const float* x      = (const float*)d_in[0];
    const float* mask   = (const float*)d_in[1];
    const float* w_qkv  = (const float*)d_in[2];
    const float* w_proj = (const float*)d_in[3];
    const float* b_proj = (const float*)d_in[4];
    float* out = (float*)d_out;

    void *qkvp_raw, *attp_raw;
    cudaGetSymbolAddress(&qkvp_raw, g_qkv_h);
    cudaGetSymbolAddress(&attp_raw, g_att);
    __half* qkvp = (__half*)qkvp_raw;
    float*  attp = (float*)attp_raw;

    cudaFuncSetAttribute(attn_kernel,
                         cudaFuncAttributeMaxDynamicSharedMemorySize,
                         ATT_SMEM_BYTES);

    // QKV: [200704,192] @ [192,576] -> fp16
    mma_gemm<__half><<<dim3(QKV_N / BN, M_TOTAL / BM), 256>>>(
        x, w_qkv, qkvp, nullptr, QKV_N);

    // Attention: one block per window
    attn_kernel<<<B_WIN, 384, ATT_SMEM_BYTES>>>(mask);

    // Proj: [200704,192] @ [192,192] + bias -> fp32 output
    mma_gemm<float><<<dim3(C_DIM / BN, M_TOTAL / BM), 256>>>(
        attp, w_proj, out, b_proj, C_DIM);
}

// round 13
// speedup vs baseline: 3.8047x; 1.3375x over previous
#include <cuda_runtime.h>
#include <cuda_fp16.h>
#include <cstdint>

// Problem constants (fixed by setup_inputs)
#define B_WIN   4096
#define NTOK    49
#define C_DIM   192
#define NHEAD   6
#define DHEAD   32
#define NWIN    64
#define M_TOTAL (B_WIN * NTOK)     // 200704 = 128 * 1568
#define QKV_N   576
#define KDIM    192

// Scratch (__device__ globals: allocation-guard-safe)
__device__ unsigned short g_x_h[(size_t)M_TOTAL * KDIM];     // x in fp16
__device__ unsigned short g_qkv_h[(size_t)M_TOTAL * QKV_N];  // qkv in fp16
__device__ unsigned short g_att_h[(size_t)M_TOTAL * C_DIM];  // attn out fp16
__device__ unsigned short g_wqkvT_h[QKV_N * KDIM];           // w_qkv^T fp16 [N][K]
__device__ unsigned short g_wprojT_h[C_DIM * KDIM];          // w_proj^T fp16 [N][K]

// pack two f32 -> f16x2 (first arg = low half)
__device__ __forceinline__ uint32_t packh2(float lo, float hi) {
    uint32_t r;
    asm("cvt.rn.f16x2.f32 %0, %1, %2;" : "=r"(r) : "f"(hi), "f"(lo));
    return r;
}

__device__ __forceinline__ uint32_t smem_u32(const void* p) {
    uint32_t a;
    asm("{ .reg .u64 t; cvta.to.shared.u64 t, %1; cvt.u32.u64 %0, t; }"
        : "=r"(a) : "l"(p));
    return a;
}

__device__ __forceinline__ void mma_f16(float* c, const uint32_t* a, const uint32_t* b) {
    asm volatile(
        "mma.sync.aligned.m16n8k16.row.col.f32.f16.f16.f32 "
        "{%0,%1,%2,%3}, {%4,%5,%6,%7}, {%8,%9}, {%0,%1,%2,%3};"
        : "+f"(c[0]), "+f"(c[1]), "+f"(c[2]), "+f"(c[3])
        : "r"(a[0]), "r"(a[1]), "r"(a[2]), "r"(a[3]), "r"(b[0]), "r"(b[1]));
}

#define LDSM_X4(r0, r1, r2, r3, addr) \
    asm volatile("ldmatrix.sync.aligned.m8n8.x4.shared.b16 {%0,%1,%2,%3}, [%4];" \
        : "=r"(r0), "=r"(r1), "=r"(r2), "=r"(r3) : "r"(addr))

#define CP_ASYNC16(dst, src) \
    asm volatile("cp.async.cg.shared.global [%0], [%1], 16;" \
        :: "r"(dst), "l"(src))
#define CP_COMMIT() asm volatile("cp.async.commit_group;")
#define CP_WAIT(n)  asm volatile("cp.async.wait_group %0;" :: "n"(n))

// Epilogue store helpers (overloaded on output type)
__device__ __forceinline__ void store2(float* C, size_t idx, float a, float b) {
    *reinterpret_cast<float2*>(C + idx) = make_float2(a, b);
}
__device__ __forceinline__ void store2(__half* C, size_t idx, float a, float b) {
    *reinterpret_cast<uint32_t*>(C + idx) = packh2(a, b);
}

// ---------------------------------------------------------------------------
// fp16 cp.async + ldmatrix GEMM: C[M,N] = A[M,192] @ WT[N,192]^T (+bias)
// CTA 128x64, BK=64 halves (3 k-tiles), 3 smem stages all prefetched.
// 256 threads, 8 warps 4m x 2n, warp tile 32x32.
// smem tile rows = 128 B; swizzle: chunk' = chunk ^ (row & 7)  (16B chunks).
// ---------------------------------------------------------------------------
#define BM 128
#define BN 64
#define BKH 64
#define STG_BYTES 24576                 // A 16384 + B 8192
#define GEMM_SMEM (3 * STG_BYTES)       // 73728

__device__ __forceinline__ void copy_tile(uint32_t sdst, const __half* A,
                                          const __half* WT, int m0, int n0,
                                          int t, int tid)
{
    const int k0 = t * BKH;
#pragma unroll
    for (int j = 0; j < 4; j++) {           // A: 128 rows x 8 chunks
        const int f = tid + j * 256;
        const int r = f >> 3, c = f & 7;
        CP_ASYNC16(sdst + r * 128 + ((c ^ (r & 7)) << 4),
                   A + (size_t)(m0 + r) * KDIM + k0 + c * 8);
    }
#pragma unroll
    for (int j = 0; j < 2; j++) {           // B: 64 n-rows x 8 chunks
        const int f = tid + j * 256;
        const int r = f >> 3, c = f & 7;
        CP_ASYNC16(sdst + 16384 + r * 128 + ((c ^ (r & 7)) << 4),
                   WT + (size_t)(n0 + r) * KDIM + k0 + c * 8);
    }
}

__device__ __forceinline__ void compute_tile(uint32_t sa, uint32_t sb,
                                             float acc[2][4][4],
                                             int wm, int wn, int lane)
{
    // ldmatrix lane->address maps (derived from validated R10 fragment layout)
    const int rAl = ((lane >> 3) & 1) * 8 + (lane & 7);   // A: m within tile
    const int cA  = lane >> 4;                            // A: k-chunk bit
    const int rBl = ((lane >> 4) & 1) * 8 + (lane & 7);   // B: n within pair
    const int cB  = (lane >> 3) & 1;                      // B: k-chunk bit
#pragma unroll
    for (int ks = 0; ks < 4; ks++) {        // four k16 steps per BK=64
        uint32_t a[2][4], bb[4][2];
#pragma unroll
        for (int mt = 0; mt < 2; mt++) {
            const int r = wm * 32 + mt * 16 + rAl;
            const uint32_t ad = sa + r * 128 + (((2 * ks + cA) ^ (r & 7)) << 4);
            LDSM_X4(a[mt][0], a[mt][1], a[mt][2], a[mt][3], ad);
        }
#pragma unroll
        for (int p = 0; p < 2; p++) {
            const int r = wn * 32 + p * 16 + rBl;
            const uint32_t ad = sb + r * 128 + (((2 * ks + cB) ^ (r & 7)) << 4);
            uint32_t r0, r1, r2, r3;
            LDSM_X4(r0, r1, r2, r3, ad);
            bb[2 * p][0] = r0;  bb[2 * p][1] = r1;
            bb[2 * p + 1][0] = r2;  bb[2 * p + 1][1] = r3;
        }
#pragma unroll
        for (int mt = 0; mt < 2; mt++)
#pragma unroll
            for (int nt = 0; nt < 4; nt++)
                mma_f16(acc[mt][nt], a[mt], bb[nt]);
    }
}

template<typename TOUT>
__global__ __launch_bounds__(256)
void mma_gemm(const __half* __restrict__ A, const __half* __restrict__ WT,
              TOUT* __restrict__ C, const float* __restrict__ bias, int N)
{
    extern __shared__ __align__(16) char dsm[];
    const uint32_t sb0 = smem_u32(dsm);

    const int tid  = threadIdx.x;
    const int wid  = tid >> 5;
    const int lane = tid & 31;
    const int grp  = lane >> 2;
    const int quad = lane & 3;
    const int wm   = wid & 3;
    const int wn   = wid >> 2;
    const int m0   = blockIdx.y * BM;
    const int n0   = blockIdx.x * BN;

    float acc[2][4][4];
#pragma unroll
    for (int mt = 0; mt < 2; mt++)
#pragma unroll
        for (int nt = 0; nt < 4; nt++)
#pragma unroll
            for (int r = 0; r < 4; r++) acc[mt][nt][r] = 0.0f;

    // Prefetch all 3 k-tiles (K=192), one commit group each.
    copy_tile(sb0,                 A, WT, m0, n0, 0, tid); CP_COMMIT();
    copy_tile(sb0 + STG_BYTES,     A, WT, m0, n0, 1, tid); CP_COMMIT();
    copy_tile(sb0 + 2 * STG_BYTES, A, WT, m0, n0, 2, tid); CP_COMMIT();

    CP_WAIT(2); __syncthreads();
    compute_tile(sb0,                 sb0 + 16384,                 acc, wm, wn, lane);
    CP_WAIT(1); __syncthreads();
    compute_tile(sb0 + STG_BYTES,     sb0 + STG_BYTES + 16384,     acc, wm, wn, lane);
    CP_WAIT(0); __syncthreads();
    compute_tile(sb0 + 2 * STG_BYTES, sb0 + 2 * STG_BYTES + 16384, acc, wm, wn, lane);

    // Epilogue: each lane-quad writes a contiguous 32 B sector.
#pragma unroll
    for (int mt = 0; mt < 2; mt++) {
#pragma unroll
        for (int nt = 0; nt < 4; nt++) {
            const int row = m0 + wm * 32 + mt * 16 + grp;
            const int col = n0 + wn * 32 + nt * 8 + quad * 2;
            float b0 = 0.f, b1 = 0.f;
            if (bias) { b0 = bias[col]; b1 = bias[col + 1]; }
            store2(C, (size_t)row * N + col,
                   acc[mt][nt][0] + b0, acc[mt][nt][1] + b1);
            store2(C, (size_t)(row + 8) * N + col,
                   acc[mt][nt][2] + b0, acc[mt][nt][3] + b1);
        }
    }
}

// ---------------------------------------------------------------------------
// Converters (run once per call, cheap)
// ---------------------------------------------------------------------------
__global__ void conv_f32_f16(const float* __restrict__ in,
                             __half* __restrict__ out, int n4)
{
    const int i = blockIdx.x * 256 + threadIdx.x;
    if (i < n4) {
        const float4 v = reinterpret_cast<const float4*>(in)[i];
        uint2 o;
        o.x = packh2(v.x, v.y);
        o.y = packh2(v.z, v.w);
        reinterpret_cast<uint2*>(out)[i] = o;
    }
}

__global__ void conv_transpose(const float* __restrict__ w,
                               __half* __restrict__ wt, int K, int N)
{
    const int i = blockIdx.x * 256 + threadIdx.x;   // i = k*N + n
    if (i < K * N) {
        const int k = i / N, n = i % N;
        wt[(size_t)n * K + k] = __float2half(w[i]);
    }
}

// ---------------------------------------------------------------------------
// Tensor-core attention (validated R12): one block per window, 384 threads =
// 6 heads x 2 warps; fragment-resident softmax; output now fp16.
// ---------------------------------------------------------------------------
#define MSW   2452
#define HEADW 3712
#define ATT_SMEM_BYTES ((MSW + 6 * HEADW) * 4)   // 98896

__global__ __launch_bounds__(384)
void attn_kernel(const float* __restrict__ mask)
{
    extern __shared__ uint32_t smw[];
    float* ms = reinterpret_cast<float*>(smw);
    const int b = blockIdx.x;
    const int tid = threadIdx.x;
    const __half* qkv = reinterpret_cast<const __half*>(g_qkv_h);
    __half* attout = reinterpret_cast<__half*>(g_att_h);

    const float* msrc = mask + (size_t)(b & (NWIN - 1)) * NTOK * NTOK;
    for (int f = tid; f < NTOK * NTOK; f += 384) {
        const int i = f / 49;
        ms[i * 50 + (f - i * 49)] = msrc[f];
    }
    for (int f = tid; f < 2352; f += 384) {
        const int h = f / 392, rem = f % 392;
        const int sel = rem / 196, r2 = rem % 196;
        const int i = r2 >> 2, c = r2 & 3;
        const uint4 v = *reinterpret_cast<const uint4*>(
            qkv + ((size_t)b * NTOK + i) * QKV_N + sel * C_DIM + h * 32 + c * 8);
        *reinterpret_cast<uint4*>(smw + MSW + h * HEADW + sel * 1280 + i * 20 + c * 4) = v;
    }
    for (int f = tid; f < 768; f += 384) {
        const int h = f / 128, rem = f % 128;
        const int jp = rem >> 2, dq = rem & 3;
        uint4 lo4 = make_uint4(0, 0, 0, 0), hi4 = make_uint4(0, 0, 0, 0);
        const __half* basep = qkv + ((size_t)b * NTOK + 2 * jp) * QKV_N
                              + 2 * C_DIM + h * 32 + dq * 8;
        if (2 * jp     < NTOK) lo4 = *reinterpret_cast<const uint4*>(basep);
        if (2 * jp + 1 < NTOK) hi4 = *reinterpret_cast<const uint4*>(basep + QKV_N);
        const __half* lo = reinterpret_cast<const __half*>(&lo4);
        const __half* hi = reinterpret_cast<const __half*>(&hi4);
        uint32_t* Vh = smw + MSW + h * HEADW + 2560;
#pragma unroll
        for (int t = 0; t < 8; t++) {
            __half2 hv = __halves2half2(lo[t], hi[t]);
            Vh[(dq * 8 + t) * 36 + jp] = *reinterpret_cast<uint32_t*>(&hv);
        }
    }
    __syncthreads();

    const int wid = tid >> 5, lane = tid & 31;
    const int g = lane >> 2, q = lane & 3;
    const int h = wid >> 1;
    const int rowbase = (wid & 1) * 32;
    const uint32_t* Qs = smw + MSW + h * HEADW;
    const uint32_t* Ks = Qs + 1280;
    const uint32_t* Vt = Qs + 2560;

    float s[2][8][4] = {};
#pragma unroll
    for (int ks = 0; ks < 2; ks++) {
        uint32_t a[2][4];
#pragma unroll
        for (int mtl = 0; mtl < 2; mtl++) {
            const int r = rowbase + mtl * 16 + g;
            a[mtl][0] = Qs[r * 20 + 8 * ks + q];
            a[mtl][1] = Qs[(r + 8) * 20 + 8 * ks + q];
            a[mtl][2] = Qs[r * 20 + 8 * ks + q + 4];
            a[mtl][3] = Qs[(r + 8) * 20 + 8 * ks + q + 4];
        }
#pragma unroll
        for (int nt = 0; nt < 8; nt++) {
            uint32_t bb[2];
            bb[0] = Ks[(8 * nt + g) * 20 + 8 * ks + q];
            bb[1] = Ks[(8 * nt + g) * 20 + 8 * ks + q + 4];
            mma_f16(s[0][nt], a[0], bb);
            mma_f16(s[1][nt], a[1], bb);
        }
    }

    const float scale = 0.17677669529663687f;
#pragma unroll
    for (int mtl = 0; mtl < 2; mtl++) {
        const int r1 = rowbase + mtl * 16 + g;
        const int rc1 = min(r1, 48) * 50, rc2 = min(r1 + 8, 48) * 50;
#pragma unroll
        for (int nt = 0; nt < 8; nt++) {
            const int j0 = 8 * nt + 2 * q, j1 = j0 + 1;
            if (j0 < NTOK) {
                s[mtl][nt][0] = fmaf(s[mtl][nt][0], scale, ms[rc1 + j0]);
                s[mtl][nt][2] = fmaf(s[mtl][nt][2], scale, ms[rc2 + j0]);
            } else { s[mtl][nt][0] = -1e30f; s[mtl][nt][2] = -1e30f; }
            if (j1 < NTOK) {
                s[mtl][nt][1] = fmaf(s[mtl][nt][1], scale, ms[rc1 + j1]);
                s[mtl][nt][3] = fmaf(s[mtl][nt][3], scale, ms[rc2 + j1]);
            } else { s[mtl][nt][1] = -1e30f; s[mtl][nt][3] = -1e30f; }
        }
    }

#pragma unroll
    for (int mtl = 0; mtl < 2; mtl++) {
        float mxA = -1e30f, mxB = -1e30f;
#pragma unroll
        for (int nt = 0; nt < 8; nt++) {
            mxA = fmaxf(mxA, fmaxf(s[mtl][nt][0], s[mtl][nt][1]));
            mxB = fmaxf(mxB, fmaxf(s[mtl][nt][2], s[mtl][nt][3]));
        }
        mxA = fmaxf(mxA, __shfl_xor_sync(0xFFFFFFFFu, mxA, 1));
        mxA = fmaxf(mxA, __shfl_xor_sync(0xFFFFFFFFu, mxA, 2));
        mxB = fmaxf(mxB, __shfl_xor_sync(0xFFFFFFFFu, mxB, 1));
        mxB = fmaxf(mxB, __shfl_xor_sync(0xFFFFFFFFu, mxB, 2));
        float sA = 0.f, sB = 0.f;
#pragma unroll
        for (int nt = 0; nt < 8; nt++) {
            s[mtl][nt][0] = __expf(s[mtl][nt][0] - mxA); sA += s[mtl][nt][0];
            s[mtl][nt][1] = __expf(s[mtl][nt][1] - mxA); sA += s[mtl][nt][1];
            s[mtl][nt][2] = __expf(s[mtl][nt][2] - mxB); sB += s[mtl][nt][2];
            s[mtl][nt][3] = __expf(s[mtl][nt][3] - mxB); sB += s[mtl][nt][3];
        }
        sA += __shfl_xor_sync(0xFFFFFFFFu, sA, 1);
        sA += __shfl_xor_sync(0xFFFFFFFFu, sA, 2);
        sB += __shfl_xor_sync(0xFFFFFFFFu, sB, 1);
        sB += __shfl_xor_sync(0xFFFFFFFFu, sB, 2);
        const float invA = 1.0f / sA, invB = 1.0f / sB;
#pragma unroll
        for (int nt = 0; nt < 8; nt++) {
            s[mtl][nt][0] *= invA; s[mtl][nt][1] *= invA;
            s[mtl][nt][2] *= invB; s[mtl][nt][3] *= invB;
        }
    }

    float o[2][4][4] = {};
#pragma unroll
    for (int ks = 0; ks < 4; ks++) {
        uint32_t pa[2][4];
#pragma unroll
        for (int mtl = 0; mtl < 2; mtl++) {
            pa[mtl][0] = packh2(s[mtl][2 * ks][0],     s[mtl][2 * ks][1]);
            pa[mtl][1] = packh2(s[mtl][2 * ks][2],     s[mtl][2 * ks][3]);
            pa[mtl][2] = packh2(s[mtl][2 * ks + 1][0], s[mtl][2 * ks + 1][1]);
            pa[mtl][3] = packh2(s[mtl][2 * ks + 1][2], s[mtl][2 * ks + 1][3]);
        }
#pragma unroll
        for (int nt2 = 0; nt2 < 4; nt2++) {
            uint32_t bb[2];
            bb[0] = Vt[(8 * nt2 + g) * 36 + 8 * ks + q];
            bb[1] = Vt[(8 * nt2 + g) * 36 + 8 * ks + q + 4];
            mma_f16(o[0][nt2], pa[0], bb);
            mma_f16(o[1][nt2], pa[1], bb);
        }
    }

    // store valid rows as fp16
#pragma unroll
    for (int mtl = 0; mtl < 2; mtl++) {
        const int r1 = rowbase + mtl * 16 + g, r2 = r1 + 8;
#pragma unroll
        for (int nt2 = 0; nt2 < 4; nt2++) {
            const int col = h * 32 + 8 * nt2 + 2 * q;
            if (r1 < NTOK)
                *reinterpret_cast<uint32_t*>(
                    attout + ((size_t)b * NTOK + r1) * C_DIM + col) =
                    packh2(o[mtl][nt2][0], o[mtl][nt2][1]);
            if (r2 < NTOK)
                *reinterpret_cast<uint32_t*>(
                    attout + ((size_t)b * NTOK + r2) * C_DIM + col) =
                    packh2(o[mtl][nt2][2], o[mtl][nt2][3]);
        }
    }
}

// ---------------------------------------------------------------------------
// Launch pipeline
// ---------------------------------------------------------------------------
extern "C" void kernel_launch(void* const* d_in, const int* in_sizes, int n_in,
                              void* d_out, int out_size)
{
    const float* x      = (const float*)d_in[0];
    const float* mask   = (const float*)d_in[1];
    const float* w_qkv  = (const float*)d_in[2];
    const float* w_proj = (const float*)d_in[3];
    const float* b_proj = (const float*)d_in[4];
    float* out = (float*)d_out;

    void *xh_r, *qkv_r, *att_r, *wq_r, *wp_r;
    cudaGetSymbolAddress(&xh_r,  g_x_h);
    cudaGetSymbolAddress(&qkv_r, g_qkv_h);
    cudaGetSymbolAddress(&att_r, g_att_h);
    cudaGetSymbolAddress(&wq_r,  g_wqkvT_h);
    cudaGetSymbolAddress(&wp_r,  g_wprojT_h);
    __half* xh    = (__half*)xh_r;
    __half* qkvp  = (__half*)qkv_r;
    __half* attp  = (__half*)att_r;
    __half* wqkvT = (__half*)wq_r;
    __half* wprojT = (__half*)wp_r;

    cudaFuncSetAttribute(mma_gemm<__half>,
                         cudaFuncAttributeMaxDynamicSharedMemorySize, GEMM_SMEM);
    cudaFuncSetAttribute(mma_gemm<float>,
                         cudaFuncAttributeMaxDynamicSharedMemorySize, GEMM_SMEM);
    cudaFuncSetAttribute(attn_kernel,
                         cudaFuncAttributeMaxDynamicSharedMemorySize, ATT_SMEM_BYTES);

    // One-time conversions
    const int n4 = M_TOTAL * KDIM / 4;   // 9633792
    conv_f32_f16<<<(n4 + 255) / 256, 256>>>(x, xh, n4);
    conv_transpose<<<(KDIM * QKV_N + 255) / 256, 256>>>(w_qkv, wqkvT, KDIM, QKV_N);
    conv_transpose<<<(KDIM * C_DIM + 255) / 256, 256>>>(w_proj, wprojT, KDIM, C_DIM);

    // QKV: [200704,192] @ [192,576] -> fp16
    mma_gemm<__half><<<dim3(QKV_N / BN, M_TOTAL / BM), 256, GEMM_SMEM>>>(
        xh, wqkvT, qkvp, nullptr, QKV_N);

    // Attention: one block per window, fp16 out
    attn_kernel<<<B_WIN, 384, ATT_SMEM_BYTES>>>(mask);

    // Proj: [200704,192] @ [192,192] + bias -> fp32 output
    mma_gemm<float><<<dim3(C_DIM / BN, M_TOTAL / BM), 256, GEMM_SMEM>>>(
        attp, wprojT, out, b_proj, C_DIM);
}

// round 14
// speedup vs baseline: 4.1024x; 1.0782x over previous
#include <cuda_runtime.h>
#include <cuda_fp16.h>
#include <cstdint>

// Problem constants (fixed by setup_inputs)
#define B_WIN   4096
#define NTOK    49
#define C_DIM   192
#define NHEAD   6
#define DHEAD   32
#define NWIN    64
#define M_TOTAL (B_WIN * NTOK)     // 200704 = 128 * 1568
#define QKV_N   576
#define KDIM    192

// Scratch (__device__ globals: allocation-guard-safe)
__device__ unsigned short g_x_h[(size_t)M_TOTAL * KDIM];     // x in fp16
__device__ unsigned short g_qkv_h[(size_t)M_TOTAL * QKV_N];  // qkv in fp16
__device__ unsigned short g_att_h[(size_t)M_TOTAL * C_DIM];  // attn out fp16
__device__ unsigned short g_wqkvT_h[QKV_N * KDIM];           // w_qkv^T fp16 [N][K]
__device__ unsigned short g_wprojT_h[C_DIM * KDIM];          // w_proj^T fp16 [N][K]

// pack two f32 -> f16x2 (first arg = low half)
__device__ __forceinline__ uint32_t packh2(float lo, float hi) {
    uint32_t r;
    asm("cvt.rn.f16x2.f32 %0, %1, %2;" : "=r"(r) : "f"(hi), "f"(lo));
    return r;
}

__device__ __forceinline__ uint32_t smem_u32(const void* p) {
    uint32_t a;
    asm("{ .reg .u64 t; cvta.to.shared.u64 t, %1; cvt.u32.u64 %0, t; }"
        : "=r"(a) : "l"(p));
    return a;
}

__device__ __forceinline__ void mma_f16(float* c, const uint32_t* a, const uint32_t* b) {
    asm volatile(
        "mma.sync.aligned.m16n8k16.row.col.f32.f16.f16.f32 "
        "{%0,%1,%2,%3}, {%4,%5,%6,%7}, {%8,%9}, {%0,%1,%2,%3};"
        : "+f"(c[0]), "+f"(c[1]), "+f"(c[2]), "+f"(c[3])
        : "r"(a[0]), "r"(a[1]), "r"(a[2]), "r"(a[3]), "r"(b[0]), "r"(b[1]));
}

#define LDSM_X4(r0, r1, r2, r3, addr) \
    asm volatile("ldmatrix.sync.aligned.m8n8.x4.shared.b16 {%0,%1,%2,%3}, [%4];" \
        : "=r"(r0), "=r"(r1), "=r"(r2), "=r"(r3) : "r"(addr))

#define CP_ASYNC16(dst, src) \
    asm volatile("cp.async.cg.shared.global [%0], [%1], 16;" \
        :: "r"(dst), "l"(src))
#define CP_COMMIT() asm volatile("cp.async.commit_group;")
#define CP_WAIT(n)  asm volatile("cp.async.wait_group %0;" :: "n"(n))

// Epilogue store helpers (overloaded on output type)
__device__ __forceinline__ void store2(float* C, size_t idx, float a, float b) {
    *reinterpret_cast<float2*>(C + idx) = make_float2(a, b);
}
__device__ __forceinline__ void store2(__half* C, size_t idx, float a, float b) {
    *reinterpret_cast<uint32_t*>(C + idx) = packh2(a, b);
}

// ---------------------------------------------------------------------------
// fp16 cp.async + ldmatrix GEMM (validated R13):
// C[M,N] = A[M,192] @ WT[N,192]^T (+bias). CTA 128x64, 3 prefetched k-stages.
// ---------------------------------------------------------------------------
#define BM 128
#define BN 64
#define BKH 64
#define STG_BYTES 24576
#define GEMM_SMEM (3 * STG_BYTES)

__device__ __forceinline__ void copy_tile(uint32_t sdst, const __half* A,
                                          const __half* WT, int m0, int n0,
                                          int t, int tid)
{
    const int k0 = t * BKH;
#pragma unroll
    for (int j = 0; j < 4; j++) {
        const int f = tid + j * 256;
        const int r = f >> 3, c = f & 7;
        CP_ASYNC16(sdst + r * 128 + ((c ^ (r & 7)) << 4),
                   A + (size_t)(m0 + r) * KDIM + k0 + c * 8);
    }
#pragma unroll
    for (int j = 0; j < 2; j++) {
        const int f = tid + j * 256;
        const int r = f >> 3, c = f & 7;
        CP_ASYNC16(sdst + 16384 + r * 128 + ((c ^ (r & 7)) << 4),
                   WT + (size_t)(n0 + r) * KDIM + k0 + c * 8);
    }
}

__device__ __forceinline__ void compute_tile(uint32_t sa, uint32_t sb,
                                             float acc[2][4][4],
                                             int wm, int wn, int lane)
{
    const int rAl = ((lane >> 3) & 1) * 8 + (lane & 7);
    const int cA  = lane >> 4;
    const int rBl = ((lane >> 4) & 1) * 8 + (lane & 7);
    const int cB  = (lane >> 3) & 1;
#pragma unroll
    for (int ks = 0; ks < 4; ks++) {
        uint32_t a[2][4], bb[4][2];
#pragma unroll
        for (int mt = 0; mt < 2; mt++) {
            const int r = wm * 32 + mt * 16 + rAl;
            const uint32_t ad = sa + r * 128 + (((2 * ks + cA) ^ (r & 7)) << 4);
            LDSM_X4(a[mt][0], a[mt][1], a[mt][2], a[mt][3], ad);
        }
#pragma unroll
        for (int p = 0; p < 2; p++) {
            const int r = wn * 32 + p * 16 + rBl;
            const uint32_t ad = sb + r * 128 + (((2 * ks + cB) ^ (r & 7)) << 4);
            uint32_t r0, r1, r2, r3;
            LDSM_X4(r0, r1, r2, r3, ad);
            bb[2 * p][0] = r0;  bb[2 * p][1] = r1;
            bb[2 * p + 1][0] = r2;  bb[2 * p + 1][1] = r3;
        }
#pragma unroll
        for (int mt = 0; mt < 2; mt++)
#pragma unroll
            for (int nt = 0; nt < 4; nt++)
                mma_f16(acc[mt][nt], a[mt], bb[nt]);
    }
}

template<typename TOUT>
__global__ __launch_bounds__(256)
void mma_gemm(const __half* __restrict__ A, const __half* __restrict__ WT,
              TOUT* __restrict__ C, const float* __restrict__ bias, int N)
{
    extern __shared__ __align__(16) char dsm[];
    const uint32_t sb0 = smem_u32(dsm);

    const int tid  = threadIdx.x;
    const int wid  = tid >> 5;
    const int lane = tid & 31;
    const int grp  = lane >> 2;
    const int quad = lane & 3;
    const int wm   = wid & 3;
    const int wn   = wid >> 2;
    const int m0   = blockIdx.y * BM;
    const int n0   = blockIdx.x * BN;

    float acc[2][4][4];
#pragma unroll
    for (int mt = 0; mt < 2; mt++)
#pragma unroll
        for (int nt = 0; nt < 4; nt++)
#pragma unroll
            for (int r = 0; r < 4; r++) acc[mt][nt][r] = 0.0f;

    copy_tile(sb0,                 A, WT, m0, n0, 0, tid); CP_COMMIT();
    copy_tile(sb0 + STG_BYTES,     A, WT, m0, n0, 1, tid); CP_COMMIT();
    copy_tile(sb0 + 2 * STG_BYTES, A, WT, m0, n0, 2, tid); CP_COMMIT();

    CP_WAIT(2); __syncthreads();
    compute_tile(sb0,                 sb0 + 16384,                 acc, wm, wn, lane);
    CP_WAIT(1); __syncthreads();
    compute_tile(sb0 + STG_BYTES,     sb0 + STG_BYTES + 16384,     acc, wm, wn, lane);
    CP_WAIT(0); __syncthreads();
    compute_tile(sb0 + 2 * STG_BYTES, sb0 + 2 * STG_BYTES + 16384, acc, wm, wn, lane);

#pragma unroll
    for (int mt = 0; mt < 2; mt++) {
#pragma unroll
        for (int nt = 0; nt < 4; nt++) {
            const int row = m0 + wm * 32 + mt * 16 + grp;
            const int col = n0 + wn * 32 + nt * 8 + quad * 2;
            float b0 = 0.f, b1 = 0.f;
            if (bias) { b0 = bias[col]; b1 = bias[col + 1]; }
            store2(C, (size_t)row * N + col,
                   acc[mt][nt][0] + b0, acc[mt][nt][1] + b1);
            store2(C, (size_t)(row + 8) * N + col,
                   acc[mt][nt][2] + b0, acc[mt][nt][3] + b1);
        }
    }
}

// ---------------------------------------------------------------------------
// Converters (run once per call, cheap)
// ---------------------------------------------------------------------------
__global__ void conv_f32_f16(const float* __restrict__ in,
                             __half* __restrict__ out, int n4)
{
    const int i = blockIdx.x * 256 + threadIdx.x;
    if (i < n4) {
        const float4 v = reinterpret_cast<const float4*>(in)[i];
        uint2 o;
        o.x = packh2(v.x, v.y);
        o.y = packh2(v.z, v.w);
        reinterpret_cast<uint2*>(out)[i] = o;
    }
}

__global__ void conv_transpose(const float* __restrict__ w,
                               __half* __restrict__ wt, int K, int N)
{
    const int i = blockIdx.x * 256 + threadIdx.x;
    if (i < K * N) {
        const int k = i / N, n = i % N;
        wt[(size_t)n * K + k] = __float2half(w[i]);
    }
}

// ---------------------------------------------------------------------------
// Tensor-core attention v3: grid (4096 windows, 3 head-pairs), 128 threads =
// 4 warps (2 heads x 2 row-halves). Per-warp fragment code identical to the
// R12/R13-validated version; smem 38.6 KB static -> 4 CTAs/SM.
// ---------------------------------------------------------------------------
#define MSW   2452
#define HEADW 3712

__global__ __launch_bounds__(128, 4)
void attn_kernel(const float* __restrict__ mask)
{
    __shared__ uint32_t smw[MSW + 2 * HEADW];   // 38608 B
    float* ms = reinterpret_cast<float*>(smw);
    const int b  = blockIdx.x;
    const int hp = blockIdx.y;          // head pair 0..2
    const int tid = threadIdx.x;
    const __half* qkv = reinterpret_cast<const __half*>(g_qkv_h);
    __half* attout = reinterpret_cast<__half*>(g_att_h);

    // ---- mask: 49x49 -> pitch 50 ----
    const float* msrc = mask + (size_t)(b & (NWIN - 1)) * NTOK * NTOK;
    for (int f = tid; f < NTOK * NTOK; f += 128) {
        const int i = f / 49;
        ms[i * 50 + (f - i * 49)] = msrc[f];
    }
    // ---- Q/K for 2 heads: 784 uint4 tasks ----
    for (int f = tid; f < 784; f += 128) {
        const int h2 = f / 392, rem = f % 392;
        const int sel = rem / 196, r2 = rem % 196;
        const int i = r2 >> 2, c = r2 & 3;
        const int gh = hp * 2 + h2;
        const uint4 v = *reinterpret_cast<const uint4*>(
            qkv + ((size_t)b * NTOK + i) * QKV_N + sel * C_DIM + gh * 32 + c * 8);
        *reinterpret_cast<uint4*>(smw + MSW + h2 * HEADW + sel * 1280 + i * 20 + c * 4) = v;
    }
    // ---- V transpose for 2 heads: 256 tasks (pads zeroed) ----
    for (int f = tid; f < 256; f += 128) {
        const int h2 = f / 128, rem = f % 128;
        const int jp = rem >> 2, dq = rem & 3;
        const int gh = hp * 2 + h2;
        uint4 lo4 = make_uint4(0, 0, 0, 0), hi4 = make_uint4(0, 0, 0, 0);
        const __half* basep = qkv + ((size_t)b * NTOK + 2 * jp) * QKV_N
                              + 2 * C_DIM + gh * 32 + dq * 8;
        if (2 * jp     < NTOK) lo4 = *reinterpret_cast<const uint4*>(basep);
        if (2 * jp + 1 < NTOK) hi4 = *reinterpret_cast<const uint4*>(basep + QKV_N);
        const __half* lo = reinterpret_cast<const __half*>(&lo4);
        const __half* hi = reinterpret_cast<const __half*>(&hi4);
        uint32_t* Vh = smw + MSW + h2 * HEADW + 2560;
#pragma unroll
        for (int t = 0; t < 8; t++) {
            __half2 hv = __halves2half2(lo[t], hi[t]);
            Vh[(dq * 8 + t) * 36 + jp] = *reinterpret_cast<uint32_t*>(&hv);
        }
    }
    __syncthreads();

    const int wid = tid >> 5, lane = tid & 31;
    const int g = lane >> 2, q = lane & 3;
    const int h2 = wid >> 1;            // local head 0/1
    const int gh = hp * 2 + h2;         // global head
    const int rowbase = (wid & 1) * 32;
    const uint32_t* Qs = smw + MSW + h2 * HEADW;
    const uint32_t* Ks = Qs + 1280;
    const uint32_t* Vt = Qs + 2560;

    // ---- S = Q K^T : 2 m-tiles x 8 n-tiles ----
    float s[2][8][4] = {};
#pragma unroll
    for (int ks = 0; ks < 2; ks++) {
        uint32_t a[2][4];
#pragma unroll
        for (int mtl = 0; mtl < 2; mtl++) {
            const int r = rowbase + mtl * 16 + g;
            a[mtl][0] = Qs[r * 20 + 8 * ks + q];
            a[mtl][1] = Qs[(r + 8) * 20 + 8 * ks + q];
            a[mtl][2] = Qs[r * 20 + 8 * ks + q + 4];
            a[mtl][3] = Qs[(r + 8) * 20 + 8 * ks + q + 4];
        }
#pragma unroll
        for (int nt = 0; nt < 8; nt++) {
            uint32_t bb[2];
            bb[0] = Ks[(8 * nt + g) * 20 + 8 * ks + q];
            bb[1] = Ks[(8 * nt + g) * 20 + 8 * ks + q + 4];
            mma_f16(s[0][nt], a[0], bb);
            mma_f16(s[1][nt], a[1], bb);
        }
    }

    // ---- scale + mask (invalid cols -> -1e30) ----
    const float scale = 0.17677669529663687f;
#pragma unroll
    for (int mtl = 0; mtl < 2; mtl++) {
        const int r1 = rowbase + mtl * 16 + g;
        const int rc1 = min(r1, 48) * 50, rc2 = min(r1 + 8, 48) * 50;
#pragma unroll
        for (int nt = 0; nt < 8; nt++) {
            const int j0 = 8 * nt + 2 * q, j1 = j0 + 1;
            if (j0 < NTOK) {
                s[mtl][nt][0] = fmaf(s[mtl][nt][0], scale, ms[rc1 + j0]);
                s[mtl][nt][2] = fmaf(s[mtl][nt][2], scale, ms[rc2 + j0]);
            } else { s[mtl][nt][0] = -1e30f; s[mtl][nt][2] = -1e30f; }
            if (j1 < NTOK) {
                s[mtl][nt][1] = fmaf(s[mtl][nt][1], scale, ms[rc1 + j1]);
                s[mtl][nt][3] = fmaf(s[mtl][nt][3], scale, ms[rc2 + j1]);
            } else { s[mtl][nt][1] = -1e30f; s[mtl][nt][3] = -1e30f; }
        }
    }

    // ---- fragment softmax (shfl xor 1,2 within lane quads) ----
#pragma unroll
    for (int mtl = 0; mtl < 2; mtl++) {
        float mxA = -1e30f, mxB = -1e30f;
#pragma unroll
        for (int nt = 0; nt < 8; nt++) {
            mxA = fmaxf(mxA, fmaxf(s[mtl][nt][0], s[mtl][nt][1]));
            mxB = fmaxf(mxB, fmaxf(s[mtl][nt][2], s[mtl][nt][3]));
        }
        mxA = fmaxf(mxA, __shfl_xor_sync(0xFFFFFFFFu, mxA, 1));
        mxA = fmaxf(mxA, __shfl_xor_sync(0xFFFFFFFFu, mxA, 2));
        mxB = fmaxf(mxB, __shfl_xor_sync(0xFFFFFFFFu, mxB, 1));
        mxB = fmaxf(mxB, __shfl_xor_sync(0xFFFFFFFFu, mxB, 2));
        float sA = 0.f, sB = 0.f;
#pragma unroll
        for (int nt = 0; nt < 8; nt++) {
            s[mtl][nt][0] = __expf(s[mtl][nt][0] - mxA); sA += s[mtl][nt][0];
            s[mtl][nt][1] = __expf(s[mtl][nt][1] - mxA); sA += s[mtl][nt][1];
            s[mtl][nt][2] = __expf(s[mtl][nt][2] - mxB); sB += s[mtl][nt][2];
            s[mtl][nt][3] = __expf(s[mtl][nt][3] - mxB); sB += s[mtl][nt][3];
        }
        sA += __shfl_xor_sync(0xFFFFFFFFu, sA, 1);
        sA += __shfl_xor_sync(0xFFFFFFFFu, sA, 2);
        sB += __shfl_xor_sync(0xFFFFFFFFu, sB, 1);
        sB += __shfl_xor_sync(0xFFFFFFFFu, sB, 2);
        const float invA = 1.0f / sA, invB = 1.0f / sB;
#pragma unroll
        for (int nt = 0; nt < 8; nt++) {
            s[mtl][nt][0] *= invA; s[mtl][nt][1] *= invA;
            s[mtl][nt][2] *= invB; s[mtl][nt][3] *= invB;
        }
    }

    // ---- O = P V : repack S C-frags as PV A-frags ----
    float o[2][4][4] = {};
#pragma unroll
    for (int ks = 0; ks < 4; ks++) {
        uint32_t pa[2][4];
#pragma unroll
        for (int mtl = 0; mtl < 2; mtl++) {
            pa[mtl][0] = packh2(s[mtl][2 * ks][0],     s[mtl][2 * ks][1]);
            pa[mtl][1] = packh2(s[mtl][2 * ks][2],     s[mtl][2 * ks][3]);
            pa[mtl][2] = packh2(s[mtl][2 * ks + 1][0], s[mtl][2 * ks + 1][1]);
            pa[mtl][3] = packh2(s[mtl][2 * ks + 1][2], s[mtl][2 * ks + 1][3]);
        }
#pragma unroll
        for (int nt2 = 0; nt2 < 4; nt2++) {
            uint32_t bb[2];
            bb[0] = Vt[(8 * nt2 + g) * 36 + 8 * ks + q];
            bb[1] = Vt[(8 * nt2 + g) * 36 + 8 * ks + q + 4];
            mma_f16(o[0][nt2], pa[0], bb);
            mma_f16(o[1][nt2], pa[1], bb);
        }
    }

    // ---- store valid rows as fp16 ----
#pragma unroll
    for (int mtl = 0; mtl < 2; mtl++) {
        const int r1 = rowbase + mtl * 16 + g, r2 = r1 + 8;
#pragma unroll
        for (int nt2 = 0; nt2 < 4; nt2++) {
            const int col = gh * 32 + 8 * nt2 + 2 * q;
            if (r1 < NTOK)
                *reinterpret_cast<uint32_t*>(
                    attout + ((size_t)b * NTOK + r1) * C_DIM + col) =
                    packh2(o[mtl][nt2][0], o[mtl][nt2][1]);
            if (r2 < NTOK)
                *reinterpret_cast<uint32_t*>(
                    attout + ((size_t)b * NTOK + r2) * C_DIM + col) =
                    packh2(o[mtl][nt2][2], o[mtl][nt2][3]);
        }
    }
}

// ---------------------------------------------------------------------------
// Launch pipeline
// ---------------------------------------------------------------------------
extern "C" void kernel_launch(void* const* d_in, const int* in_sizes, int n_in,
                              void* d_out, int out_size)
{
    const float* x      = (const float*)d_in[0];
    const float* mask   = (const float*)d_in[1];
    const float* w_qkv  = (const float*)d_in[2];
    const float* w_proj = (const float*)d_in[3];
    const float* b_proj = (const float*)d_in[4];
    float* out = (float*)d_out;

    void *xh_r, *qkv_r, *att_r, *wq_r, *wp_r;
    cudaGetSymbolAddress(&xh_r,  g_x_h);
    cudaGetSymbolAddress(&qkv_r, g_qkv_h);
    cudaGetSymbolAddress(&att_r, g_att_h);
    cudaGetSymbolAddress(&wq_r,  g_wqkvT_h);
    cudaGetSymbolAddress(&wp_r,  g_wprojT_h);
    __half* xh    = (__half*)xh_r;
    __half* qkvp  = (__half*)qkv_r;
    __half* attp  = (__half*)att_r;
    __half* wqkvT = (__half*)wq_r;
    __half* wprojT = (__half*)wp_r;

    cudaFuncSetAttribute(mma_gemm<__half>,
                         cudaFuncAttributeMaxDynamicSharedMemorySize, GEMM_SMEM);
    cudaFuncSetAttribute(mma_gemm<float>,
                         cudaFuncAttributeMaxDynamicSharedMemorySize, GEMM_SMEM);

    // One-time conversions
    const int n4 = M_TOTAL * KDIM / 4;
    conv_f32_f16<<<(n4 + 255) / 256, 256>>>(x, xh, n4);
    conv_transpose<<<(KDIM * QKV_N + 255) / 256, 256>>>(w_qkv, wqkvT, KDIM, QKV_N);
    conv_transpose<<<(KDIM * C_DIM + 255) / 256, 256>>>(w_proj, wprojT, KDIM, C_DIM);

    // QKV: [200704,192] @ [192,576] -> fp16
    mma_gemm<__half><<<dim3(QKV_N / BN, M_TOTAL / BM), 256, GEMM_SMEM>>>(
        xh, wqkvT, qkvp, nullptr, QKV_N);

    // Attention: (window, head-pair) grid, 4 CTAs/SM
    attn_kernel<<<dim3(B_WIN, 3), 128>>>(mask);

    // Proj: [200704,192] @ [192,192] + bias -> fp32 output
    mma_gemm<float><<<dim3(C_DIM / BN, M_TOTAL / BM), 256, GEMM_SMEM>>>(
        attp, wprojT, out, b_proj, C_DIM);
}

// round 15
// speedup vs baseline: 4.4303x; 1.0799x over previous
#include <cuda_runtime.h>
#include <cuda_fp16.h>
#include <cstdint>

// Problem constants (fixed by setup_inputs)
#define B_WIN   4096
#define NTOK    49
#define C_DIM   192
#define NHEAD   6
#define DHEAD   32
#define NWIN    64
#define M_TOTAL (B_WIN * NTOK)     // 200704 = 256 * 784
#define QKV_N   576
#define KDIM    192

// Scratch (__device__ globals: allocation-guard-safe)
__device__ unsigned short g_x_h[(size_t)M_TOTAL * KDIM];     // x in fp16
__device__ unsigned short g_qkv_h[(size_t)M_TOTAL * QKV_N];  // qkv in fp16
__device__ unsigned short g_att_h[(size_t)M_TOTAL * C_DIM];  // attn out fp16
__device__ unsigned short g_wqkvT_h[QKV_N * KDIM];           // w_qkv^T fp16 [N][K]
__device__ unsigned short g_wprojT_h[C_DIM * KDIM];          // w_proj^T fp16 [N][K]

__device__ __forceinline__ uint32_t packh2(float lo, float hi) {
    uint32_t r;
    asm("cvt.rn.f16x2.f32 %0, %1, %2;" : "=r"(r) : "f"(hi), "f"(lo));
    return r;
}

__device__ __forceinline__ uint32_t smem_u32(const void* p) {
    uint32_t a;
    asm("{ .reg .u64 t; cvta.to.shared.u64 t, %1; cvt.u32.u64 %0, t; }"
        : "=r"(a) : "l"(p));
    return a;
}

__device__ __forceinline__ void mma_f16(float* c, const uint32_t* a, const uint32_t* b) {
    asm volatile(
        "mma.sync.aligned.m16n8k16.row.col.f32.f16.f16.f32 "
        "{%0,%1,%2,%3}, {%4,%5,%6,%7}, {%8,%9}, {%0,%1,%2,%3};"
        : "+f"(c[0]), "+f"(c[1]), "+f"(c[2]), "+f"(c[3])
        : "r"(a[0]), "r"(a[1]), "r"(a[2]), "r"(a[3]), "r"(b[0]), "r"(b[1]));
}

#define LDSM_X4(r0, r1, r2, r3, addr) \
    asm volatile("ldmatrix.sync.aligned.m8n8.x4.shared.b16 {%0,%1,%2,%3}, [%4];" \
        : "=r"(r0), "=r"(r1), "=r"(r2), "=r"(r3) : "r"(addr))

#define CP_ASYNC16(dst, src) \
    asm volatile("cp.async.cg.shared.global [%0], [%1], 16;" \
        :: "r"(dst), "l"(src))
#define CP_COMMIT() asm volatile("cp.async.commit_group;")
#define CP_WAIT(n)  asm volatile("cp.async.wait_group %0;" :: "n"(n))

__device__ __forceinline__ void store2(float* C, size_t idx, float a, float b) {
    *reinterpret_cast<float2*>(C + idx) = make_float2(a, b);
}
__device__ __forceinline__ void store2(__half* C, size_t idx, float a, float b) {
    *reinterpret_cast<uint32_t*>(C + idx) = packh2(a, b);
}

// ---------------------------------------------------------------------------
// fp16 cp.async + ldmatrix GEMM v2: CTA 256x64, warp tile 64x32 (8 warps,
// 4m x 2n), BK=64 halves, 2 smem stages rotating over 3 k-tiles.
// Swizzle: 16B chunk' = chunk ^ (row & 7).
// ---------------------------------------------------------------------------
#define BM 256
#define BN 64
#define BKH 64
#define STG_BYTES 40960                 // A 32768 + B 8192
#define GEMM_SMEM (2 * STG_BYTES)       // 81920

__device__ __forceinline__ void copy_tile(uint32_t sdst, const __half* A,
                                          const __half* WT, int m0, int n0,
                                          int t, int tid)
{
    const int k0 = t * BKH;
#pragma unroll
    for (int j = 0; j < 8; j++) {           // A: 256 rows x 8 chunks
        const int f = tid + j * 256;
        const int r = f >> 3, c = f & 7;
        CP_ASYNC16(sdst + r * 128 + ((c ^ (r & 7)) << 4),
                   A + (size_t)(m0 + r) * KDIM + k0 + c * 8);
    }
#pragma unroll
    for (int j = 0; j < 2; j++) {           // B: 64 n-rows x 8 chunks
        const int f = tid + j * 256;
        const int r = f >> 3, c = f & 7;
        CP_ASYNC16(sdst + 32768 + r * 128 + ((c ^ (r & 7)) << 4),
                   WT + (size_t)(n0 + r) * KDIM + k0 + c * 8);
    }
}

__device__ __forceinline__ void compute_tile(uint32_t sa, uint32_t sb,
                                             float acc[4][4][4],
                                             int wm, int wn, int lane)
{
    const int rAl = ((lane >> 3) & 1) * 8 + (lane & 7);
    const int cA  = lane >> 4;
    const int rBl = ((lane >> 4) & 1) * 8 + (lane & 7);
    const int cB  = (lane >> 3) & 1;
#pragma unroll
    for (int ks = 0; ks < 4; ks++) {
        uint32_t a[4][4], bb[4][2];
#pragma unroll
        for (int mt = 0; mt < 4; mt++) {
            const int r = wm * 64 + mt * 16 + rAl;
            const uint32_t ad = sa + r * 128 + (((2 * ks + cA) ^ (r & 7)) << 4);
            LDSM_X4(a[mt][0], a[mt][1], a[mt][2], a[mt][3], ad);
        }
#pragma unroll
        for (int p = 0; p < 2; p++) {
            const int r = wn * 32 + p * 16 + rBl;
            const uint32_t ad = sb + r * 128 + (((2 * ks + cB) ^ (r & 7)) << 4);
            uint32_t r0, r1, r2, r3;
            LDSM_X4(r0, r1, r2, r3, ad);
            bb[2 * p][0] = r0;  bb[2 * p][1] = r1;
            bb[2 * p + 1][0] = r2;  bb[2 * p + 1][1] = r3;
        }
#pragma unroll
        for (int mt = 0; mt < 4; mt++)
#pragma unroll
            for (int nt = 0; nt < 4; nt++)
                mma_f16(acc[mt][nt], a[mt], bb[nt]);
    }
}

template<typename TOUT>
__global__ __launch_bounds__(256, 2)
void mma_gemm(const __half* __restrict__ A, const __half* __restrict__ WT,
              TOUT* __restrict__ C, const float* __restrict__ bias, int N)
{
    extern __shared__ __align__(16) char dsm[];
    const uint32_t sb0 = smem_u32(dsm);
    const uint32_t sb1 = sb0 + STG_BYTES;

    const int tid  = threadIdx.x;
    const int wid  = tid >> 5;
    const int lane = tid & 31;
    const int grp  = lane >> 2;
    const int quad = lane & 3;
    const int wm   = wid & 3;        // 4 m-warps (64 rows each)
    const int wn   = wid >> 2;       // 2 n-warps (32 cols each)
    const int m0   = blockIdx.y * BM;
    const int n0   = blockIdx.x * BN;

    float acc[4][4][4];
#pragma unroll
    for (int mt = 0; mt < 4; mt++)
#pragma unroll
        for (int nt = 0; nt < 4; nt++)
#pragma unroll
            for (int r = 0; r < 4; r++) acc[mt][nt][r] = 0.0f;

    copy_tile(sb0, A, WT, m0, n0, 0, tid); CP_COMMIT();
    copy_tile(sb1, A, WT, m0, n0, 1, tid); CP_COMMIT();

    CP_WAIT(1); __syncthreads();
    compute_tile(sb0, sb0 + 32768, acc, wm, wn, lane);
    __syncthreads();                                   // all readers done w/ s0
    copy_tile(sb0, A, WT, m0, n0, 2, tid); CP_COMMIT();
    CP_WAIT(1); __syncthreads();
    compute_tile(sb1, sb1 + 32768, acc, wm, wn, lane);
    CP_WAIT(0); __syncthreads();
    compute_tile(sb0, sb0 + 32768, acc, wm, wn, lane);

#pragma unroll
    for (int mt = 0; mt < 4; mt++) {
#pragma unroll
        for (int nt = 0; nt < 4; nt++) {
            const int row = m0 + wm * 64 + mt * 16 + grp;
            const int col = n0 + wn * 32 + nt * 8 + quad * 2;
            float b0 = 0.f, b1 = 0.f;
            if (bias) { b0 = bias[col]; b1 = bias[col + 1]; }
            store2(C, (size_t)row * N + col,
                   acc[mt][nt][0] + b0, acc[mt][nt][1] + b1);
            store2(C, (size_t)(row + 8) * N + col,
                   acc[mt][nt][2] + b0, acc[mt][nt][3] + b1);
        }
    }
}

// ---------------------------------------------------------------------------
// Converters (once per call, bandwidth-bound)
// ---------------------------------------------------------------------------
__global__ void conv_f32_f16(const float* __restrict__ in,
                             __half* __restrict__ out, int n4)
{
    const int i = blockIdx.x * 256 + threadIdx.x;
    if (i < n4) {
        const float4 v = reinterpret_cast<const float4*>(in)[i];
        uint2 o;
        o.x = packh2(v.x, v.y);
        o.y = packh2(v.z, v.w);
        reinterpret_cast<uint2*>(out)[i] = o;
    }
}

__global__ void conv_transpose(const float* __restrict__ w,
                               __half* __restrict__ wt, int K, int N)
{
    const int i = blockIdx.x * 256 + threadIdx.x;
    if (i < K * N) {
        const int k = i / N, n = i % N;
        wt[(size_t)n * K + k] = __float2half(w[i]);
    }
}

// ---------------------------------------------------------------------------
// Tensor-core attention v4: grid (4096 windows, 6 heads), 64 threads =
// 2 warps (row-halves). Per-warp fragment code identical to validated R12-14.
// Mask read directly from global (L2-resident) in the scale step.
// smem: Qs[49x pitch20]@0 (1280 w), Ks@1280, Vt[32d x pitch36]@2560 -> 3712 w.
// ---------------------------------------------------------------------------
#define HEADW 3712

__global__ __launch_bounds__(64, 8)
void attn_kernel(const float* __restrict__ mask)
{
    __shared__ uint32_t smw[HEADW];     // 14848 B
    const int b  = blockIdx.x;
    const int gh = blockIdx.y;          // head 0..5
    const int tid = threadIdx.x;        // 0..63
    const __half* qkv = reinterpret_cast<const __half*>(g_qkv_h);
    __half* attout = reinterpret_cast<__half*>(g_att_h);

    // ---- Q/K staging: 392 uint4 tasks ----
    for (int f = tid; f < 392; f += 64) {
        const int sel = f / 196, r2 = f % 196;
        const int i = r2 >> 2, c = r2 & 3;
        const uint4 v = *reinterpret_cast<const uint4*>(
            qkv + ((size_t)b * NTOK + i) * QKV_N + sel * C_DIM + gh * 32 + c * 8);
        *reinterpret_cast<uint4*>(smw + sel * 1280 + i * 20 + c * 4) = v;
    }
    // ---- V transpose: 128 tasks (pads zeroed) ----
    for (int f = tid; f < 128; f += 64) {
        const int jp = f >> 2, dq = f & 3;
        uint4 lo4 = make_uint4(0, 0, 0, 0), hi4 = make_uint4(0, 0, 0, 0);
        const __half* basep = qkv + ((size_t)b * NTOK + 2 * jp) * QKV_N
                              + 2 * C_DIM + gh * 32 + dq * 8;
        if (2 * jp     < NTOK) lo4 = *reinterpret_cast<const uint4*>(basep);
        if (2 * jp + 1 < NTOK) hi4 = *reinterpret_cast<const uint4*>(basep + QKV_N);
        const __half* lo = reinterpret_cast<const __half*>(&lo4);
        const __half* hi = reinterpret_cast<const __half*>(&hi4);
        uint32_t* Vh = smw + 2560;
#pragma unroll
        for (int t = 0; t < 8; t++) {
            __half2 hv = __halves2half2(lo[t], hi[t]);
            Vh[(dq * 8 + t) * 36 + jp] = *reinterpret_cast<uint32_t*>(&hv);
        }
    }
    __syncthreads();

    const int wid = tid >> 5, lane = tid & 31;
    const int g = lane >> 2, q = lane & 3;
    const int rowbase = wid * 32;
    const uint32_t* Qs = smw;
    const uint32_t* Ks = smw + 1280;
    const uint32_t* Vt = smw + 2560;

    // ---- S = Q K^T : 2 m-tiles x 8 n-tiles ----
    float s[2][8][4] = {};
#pragma unroll
    for (int ks = 0; ks < 2; ks++) {
        uint32_t a[2][4];
#pragma unroll
        for (int mtl = 0; mtl < 2; mtl++) {
            const int r = rowbase + mtl * 16 + g;
            a[mtl][0] = Qs[r * 20 + 8 * ks + q];
            a[mtl][1] = Qs[(r + 8) * 20 + 8 * ks + q];
            a[mtl][2] = Qs[r * 20 + 8 * ks + q + 4];
            a[mtl][3] = Qs[(r + 8) * 20 + 8 * ks + q + 4];
        }
#pragma unroll
        for (int nt = 0; nt < 8; nt++) {
            uint32_t bb[2];
            bb[0] = Ks[(8 * nt + g) * 20 + 8 * ks + q];
            bb[1] = Ks[(8 * nt + g) * 20 + 8 * ks + q + 4];
            mma_f16(s[0][nt], a[0], bb);
            mma_f16(s[1][nt], a[1], bb);
        }
    }

    // ---- scale + mask from global (L2-resident); invalid cols -> -1e30 ----
    const float scale = 0.17677669529663687f;
    const float* mrow = mask + (size_t)(b & (NWIN - 1)) * NTOK * NTOK;
#pragma unroll
    for (int mtl = 0; mtl < 2; mtl++) {
        const int r1 = rowbase + mtl * 16 + g;
        const float* m1 = mrow + min(r1, 48) * NTOK;
        const float* m2 = mrow + min(r1 + 8, 48) * NTOK;
#pragma unroll
        for (int nt = 0; nt < 8; nt++) {
            const int j0 = 8 * nt + 2 * q, j1 = j0 + 1;
            if (j0 < NTOK) {
                s[mtl][nt][0] = fmaf(s[mtl][nt][0], scale, m1[j0]);
                s[mtl][nt][2] = fmaf(s[mtl][nt][2], scale, m2[j0]);
            } else { s[mtl][nt][0] = -1e30f; s[mtl][nt][2] = -1e30f; }
            if (j1 < NTOK) {
                s[mtl][nt][1] = fmaf(s[mtl][nt][1], scale, m1[j1]);
                s[mtl][nt][3] = fmaf(s[mtl][nt][3], scale, m2[j1]);
            } else { s[mtl][nt][1] = -1e30f; s[mtl][nt][3] = -1e30f; }
        }
    }

    // ---- fragment softmax (shfl xor 1,2 within lane quads) ----
#pragma unroll
    for (int mtl = 0; mtl < 2; mtl++) {
        float mxA = -1e30f, mxB = -1e30f;
#pragma unroll
        for (int nt = 0; nt < 8; nt++) {
            mxA = fmaxf(mxA, fmaxf(s[mtl][nt][0], s[mtl][nt][1]));
            mxB = fmaxf(mxB, fmaxf(s[mtl][nt][2], s[mtl][nt][3]));
        }
        mxA = fmaxf(mxA, __shfl_xor_sync(0xFFFFFFFFu, mxA, 1));
        mxA = fmaxf(mxA, __shfl_xor_sync(0xFFFFFFFFu, mxA, 2));
        mxB = fmaxf(mxB, __shfl_xor_sync(0xFFFFFFFFu, mxB, 1));
        mxB = fmaxf(mxB, __shfl_xor_sync(0xFFFFFFFFu, mxB, 2));
        float sA = 0.f, sB = 0.f;
#pragma unroll
        for (int nt = 0; nt < 8; nt++) {
            s[mtl][nt][0] = __expf(s[mtl][nt][0] - mxA); sA += s[mtl][nt][0];
            s[mtl][nt][1] = __expf(s[mtl][nt][1] - mxA); sA += s[mtl][nt][1];
            s[mtl][nt][2] = __expf(s[mtl][nt][2] - mxB); sB += s[mtl][nt][2];
            s[mtl][nt][3] = __expf(s[mtl][nt][3] - mxB); sB += s[mtl][nt][3];
        }
        sA += __shfl_xor_sync(0xFFFFFFFFu, sA, 1);
        sA += __shfl_xor_sync(0xFFFFFFFFu, sA, 2);
        sB += __shfl_xor_sync(0xFFFFFFFFu, sB, 1);
        sB += __shfl_xor_sync(0xFFFFFFFFu, sB, 2);
        const float invA = 1.0f / sA, invB = 1.0f / sB;
#pragma unroll
        for (int nt = 0; nt < 8; nt++) {
            s[mtl][nt][0] *= invA; s[mtl][nt][1] *= invA;
            s[mtl][nt][2] *= invB; s[mtl][nt][3] *= invB;
        }
    }

    // ---- O = P V : repack S C-frags as PV A-frags ----
    float o[2][4][4] = {};
#pragma unroll
    for (int ks = 0; ks < 4; ks++) {
        uint32_t pa[2][4];
#pragma unroll
        for (int mtl = 0; mtl < 2; mtl++) {
            pa[mtl][0] = packh2(s[mtl][2 * ks][0],     s[mtl][2 * ks][1]);
            pa[mtl][1] = packh2(s[mtl][2 * ks][2],     s[mtl][2 * ks][3]);
            pa[mtl][2] = packh2(s[mtl][2 * ks + 1][0], s[mtl][2 * ks + 1][1]);
            pa[mtl][3] = packh2(s[mtl][2 * ks + 1][2], s[mtl][2 * ks + 1][3]);
        }
#pragma unroll
        for (int nt2 = 0; nt2 < 4; nt2++) {
            uint32_t bb[2];
            bb[0] = Vt[(8 * nt2 + g) * 36 + 8 * ks + q];
            bb[1] = Vt[(8 * nt2 + g) * 36 + 8 * ks + q + 4];
            mma_f16(o[0][nt2], pa[0], bb);
            mma_f16(o[1][nt2], pa[1], bb);
        }
    }

    // ---- store valid rows as fp16 ----
#pragma unroll
    for (int mtl = 0; mtl < 2; mtl++) {
        const int r1 = rowbase + mtl * 16 + g, r2 = r1 + 8;
#pragma unroll
        for (int nt2 = 0; nt2 < 4; nt2++) {
            const int col = gh * 32 + 8 * nt2 + 2 * q;
            if (r1 < NTOK)
                *reinterpret_cast<uint32_t*>(
                    attout + ((size_t)b * NTOK + r1) * C_DIM + col) =
                    packh2(o[mtl][nt2][0], o[mtl][nt2][1]);
            if (r2 < NTOK)
                *reinterpret_cast<uint32_t*>(
                    attout + ((size_t)b * NTOK + r2) * C_DIM + col) =
                    packh2(o[mtl][nt2][2], o[mtl][nt2][3]);
        }
    }
}

// ---------------------------------------------------------------------------
// Launch pipeline
// ---------------------------------------------------------------------------
extern "C" void kernel_launch(void* const* d_in, const int* in_sizes, int n_in,
                              void* d_out, int out_size)
{
    const float* x      = (const float*)d_in[0];
    const float* mask   = (const float*)d_in[1];
    const float* w_qkv  = (const float*)d_in[2];
    const float* w_proj = (const float*)d_in[3];
    const float* b_proj = (const float*)d_in[4];
    float* out = (float*)d_out;

    void *xh_r, *qkv_r, *att_r, *wq_r, *wp_r;
    cudaGetSymbolAddress(&xh_r,  g_x_h);
    cudaGetSymbolAddress(&qkv_r, g_qkv_h);
    cudaGetSymbolAddress(&att_r, g_att_h);
    cudaGetSymbolAddress(&wq_r,  g_wqkvT_h);
    cudaGetSymbolAddress(&wp_r,  g_wprojT_h);
    __half* xh    = (__half*)xh_r;
    __half* qkvp  = (__half*)qkv_r;
    __half* attp  = (__half*)att_r;
    __half* wqkvT = (__half*)wq_r;
    __half* wprojT = (__half*)wp_r;

    cudaFuncSetAttribute(mma_gemm<__half>,
                         cudaFuncAttributeMaxDynamicSharedMemorySize, GEMM_SMEM);
    cudaFuncSetAttribute(mma_gemm<float>,
                         cudaFuncAttributeMaxDynamicSharedMemorySize, GEMM_SMEM);

    // One-time conversions
    const int n4 = M_TOTAL * KDIM / 4;
    conv_f32_f16<<<(n4 + 255) / 256, 256>>>(x, xh, n4);
    conv_transpose<<<(KDIM * QKV_N + 255) / 256, 256>>>(w_qkv, wqkvT, KDIM, QKV_N);
    conv_transpose<<<(KDIM * C_DIM + 255) / 256, 256>>>(w_proj, wprojT, KDIM, C_DIM);

    // QKV: [200704,192] @ [192,576] -> fp16
    mma_gemm<__half><<<dim3(QKV_N / BN, M_TOTAL / BM), 256, GEMM_SMEM>>>(
        xh, wqkvT, qkvp, nullptr, QKV_N);

    // Attention: (window, head) grid, 64-thread CTAs, 8/SM
    attn_kernel<<<dim3(B_WIN, NHEAD), 64>>>(mask);

    // Proj: [200704,192] @ [192,192] + bias -> fp32 output
    mma_gemm<float><<<dim3(C_DIM / BN, M_TOTAL / BM), 256, GEMM_SMEM>>>(
        attp, wprojT, out, b_proj, C_DIM);
}

// round 16
// speedup vs baseline: 4.9595x; 1.1195x over previous
#include <cuda_runtime.h>
#include <cuda_fp16.h>
#include <cstdint>

// Problem constants (fixed by setup_inputs)
#define B_WIN   4096
#define NTOK    49
#define C_DIM   192
#define NHEAD   6
#define DHEAD   32
#define NWIN    64
#define M_TOTAL (B_WIN * NTOK)     // 200704 = 256 * 784
#define QKV_N   576
#define KDIM    192

// Scratch (__device__ globals: allocation-guard-safe)
__device__ unsigned short g_x_h[(size_t)M_TOTAL * KDIM];     // x in fp16
__device__ unsigned short g_qkv_h[(size_t)M_TOTAL * QKV_N];  // qkv in fp16
__device__ unsigned short g_att_h[(size_t)M_TOTAL * C_DIM];  // attn out fp16
__device__ unsigned short g_wqkvT_h[QKV_N * KDIM];           // w_qkv^T fp16 [N][K]
__device__ unsigned short g_wprojT_h[C_DIM * KDIM];          // w_proj^T fp16 [N][K]

__device__ __forceinline__ uint32_t packh2(float lo, float hi) {
    uint32_t r;
    asm("cvt.rn.f16x2.f32 %0, %1, %2;" : "=r"(r) : "f"(hi), "f"(lo));
    return r;
}

__device__ __forceinline__ uint32_t smem_u32(const void* p) {
    uint32_t a;
    asm("{ .reg .u64 t; cvta.to.shared.u64 t, %1; cvt.u32.u64 %0, t; }"
        : "=r"(a) : "l"(p));
    return a;
}

__device__ __forceinline__ void mma_f16(float* c, const uint32_t* a, const uint32_t* b) {
    asm volatile(
        "mma.sync.aligned.m16n8k16.row.col.f32.f16.f16.f32 "
        "{%0,%1,%2,%3}, {%4,%5,%6,%7}, {%8,%9}, {%0,%1,%2,%3};"
        : "+f"(c[0]), "+f"(c[1]), "+f"(c[2]), "+f"(c[3])
        : "r"(a[0]), "r"(a[1]), "r"(a[2]), "r"(a[3]), "r"(b[0]), "r"(b[1]));
}

#define LDSM_X4(r0, r1, r2, r3, addr) \
    asm volatile("ldmatrix.sync.aligned.m8n8.x4.shared.b16 {%0,%1,%2,%3}, [%4];" \
        : "=r"(r0), "=r"(r1), "=r"(r2), "=r"(r3) : "r"(addr))

#define CP_ASYNC16(dst, src) \
    asm volatile("cp.async.cg.shared.global [%0], [%1], 16;" \
        :: "r"(dst), "l"(src))
#define CP_COMMIT() asm volatile("cp.async.commit_group;")
#define CP_WAIT(n)  asm volatile("cp.async.wait_group %0;" :: "n"(n))

__device__ __forceinline__ void store2(float* C, size_t idx, float a, float b) {
    *reinterpret_cast<float2*>(C + idx) = make_float2(a, b);
}
__device__ __forceinline__ void store2(__half* C, size_t idx, float a, float b) {
    *reinterpret_cast<uint32_t*>(C + idx) = packh2(a, b);
}

// ---------------------------------------------------------------------------
// fp16 cp.async + ldmatrix GEMM (validated R15): CTA 256x64, warp tile 64x32,
// BK=64 halves, 2 smem stages rotating over 3 k-tiles.
// ---------------------------------------------------------------------------
#define BM 256
#define BN 64
#define BKH 64
#define STG_BYTES 40960                 // A 32768 + B 8192
#define GEMM_SMEM (2 * STG_BYTES)       // 81920

__device__ __forceinline__ void copy_tile(uint32_t sdst, const __half* A,
                                          const __half* WT, int m0, int n0,
                                          int t, int tid)
{
    const int k0 = t * BKH;
#pragma unroll
    for (int j = 0; j < 8; j++) {
        const int f = tid + j * 256;
        const int r = f >> 3, c = f & 7;
        CP_ASYNC16(sdst + r * 128 + ((c ^ (r & 7)) << 4),
                   A + (size_t)(m0 + r) * KDIM + k0 + c * 8);
    }
#pragma unroll
    for (int j = 0; j < 2; j++) {
        const int f = tid + j * 256;
        const int r = f >> 3, c = f & 7;
        CP_ASYNC16(sdst + 32768 + r * 128 + ((c ^ (r & 7)) << 4),
                   WT + (size_t)(n0 + r) * KDIM + k0 + c * 8);
    }
}

__device__ __forceinline__ void compute_tile(uint32_t sa, uint32_t sb,
                                             float acc[4][4][4],
                                             int wm, int wn, int lane)
{
    const int rAl = ((lane >> 3) & 1) * 8 + (lane & 7);
    const int cA  = lane >> 4;
    const int rBl = ((lane >> 4) & 1) * 8 + (lane & 7);
    const int cB  = (lane >> 3) & 1;
#pragma unroll
    for (int ks = 0; ks < 4; ks++) {
        uint32_t a[4][4], bb[4][2];
#pragma unroll
        for (int mt = 0; mt < 4; mt++) {
            const int r = wm * 64 + mt * 16 + rAl;
            const uint32_t ad = sa + r * 128 + (((2 * ks + cA) ^ (r & 7)) << 4);
            LDSM_X4(a[mt][0], a[mt][1], a[mt][2], a[mt][3], ad);
        }
#pragma unroll
        for (int p = 0; p < 2; p++) {
            const int r = wn * 32 + p * 16 + rBl;
            const uint32_t ad = sb + r * 128 + (((2 * ks + cB) ^ (r & 7)) << 4);
            uint32_t r0, r1, r2, r3;
            LDSM_X4(r0, r1, r2, r3, ad);
            bb[2 * p][0] = r0;  bb[2 * p][1] = r1;
            bb[2 * p + 1][0] = r2;  bb[2 * p + 1][1] = r3;
        }
#pragma unroll
        for (int mt = 0; mt < 4; mt++)
#pragma unroll
            for (int nt = 0; nt < 4; nt++)
                mma_f16(acc[mt][nt], a[mt], bb[nt]);
    }
}

template<typename TOUT>
__global__ __launch_bounds__(256, 2)
void mma_gemm(const __half* __restrict__ A, const __half* __restrict__ WT,
              TOUT* __restrict__ C, const float* __restrict__ bias, int N)
{
    extern __shared__ __align__(16) char dsm[];
    const uint32_t sb0 = smem_u32(dsm);
    const uint32_t sb1 = sb0 + STG_BYTES;

    const int tid  = threadIdx.x;
    const int wid  = tid >> 5;
    const int lane = tid & 31;
    const int grp  = lane >> 2;
    const int quad = lane & 3;
    const int wm   = wid & 3;
    const int wn   = wid >> 2;
    const int m0   = blockIdx.y * BM;
    const int n0   = blockIdx.x * BN;

    float acc[4][4][4];
#pragma unroll
    for (int mt = 0; mt < 4; mt++)
#pragma unroll
        for (int nt = 0; nt < 4; nt++)
#pragma unroll
            for (int r = 0; r < 4; r++) acc[mt][nt][r] = 0.0f;

    copy_tile(sb0, A, WT, m0, n0, 0, tid); CP_COMMIT();
    copy_tile(sb1, A, WT, m0, n0, 1, tid); CP_COMMIT();

    CP_WAIT(1); __syncthreads();
    compute_tile(sb0, sb0 + 32768, acc, wm, wn, lane);
    __syncthreads();
    copy_tile(sb0, A, WT, m0, n0, 2, tid); CP_COMMIT();
    CP_WAIT(1); __syncthreads();
    compute_tile(sb1, sb1 + 32768, acc, wm, wn, lane);
    CP_WAIT(0); __syncthreads();
    compute_tile(sb0, sb0 + 32768, acc, wm, wn, lane);

#pragma unroll
    for (int mt = 0; mt < 4; mt++) {
#pragma unroll
        for (int nt = 0; nt < 4; nt++) {
            const int row = m0 + wm * 64 + mt * 16 + grp;
            const int col = n0 + wn * 32 + nt * 8 + quad * 2;
            float b0 = 0.f, b1 = 0.f;
            if (bias) { b0 = bias[col]; b1 = bias[col + 1]; }
            store2(C, (size_t)row * N + col,
                   acc[mt][nt][0] + b0, acc[mt][nt][1] + b1);
            store2(C, (size_t)(row + 8) * N + col,
                   acc[mt][nt][2] + b0, acc[mt][nt][3] + b1);
        }
    }
}

// ---------------------------------------------------------------------------
// Converters (once per call, bandwidth-bound)
// ---------------------------------------------------------------------------
__global__ void conv_f32_f16(const float* __restrict__ in,
                             __half* __restrict__ out, int n4)
{
    const int i = blockIdx.x * 256 + threadIdx.x;
    if (i < n4) {
        const float4 v = reinterpret_cast<const float4*>(in)[i];
        uint2 o;
        o.x = packh2(v.x, v.y);
        o.y = packh2(v.z, v.w);
        reinterpret_cast<uint2*>(out)[i] = o;
    }
}

// Both weight transposes in one launch.
__global__ void conv_transpose2(const float* __restrict__ w1, __half* __restrict__ wt1,
                                const float* __restrict__ w2, __half* __restrict__ wt2)
{
    const int i = blockIdx.x * 256 + threadIdx.x;
    const int n1 = KDIM * QKV_N;               // 110592
    if (i < n1) {
        const int k = i / QKV_N, n = i % QKV_N;
        wt1[(size_t)n * KDIM + k] = __float2half(w1[i]);
    } else if (i < n1 + KDIM * C_DIM) {
        const int j = i - n1;
        const int k = j / C_DIM, n = j % C_DIM;
        wt2[(size_t)n * KDIM + k] = __float2half(w2[j]);
    }
}

// ---------------------------------------------------------------------------
// Tensor-core attention v5: grid (4096 windows, 6 heads), 64 threads.
// Q/K staged via cp.async (pure 16B copies, all offsets 16B-aligned);
// V LDG+pack+STS issued after the cp.asyncs so its latency overlaps the DMA.
// Per-warp fragment code identical to validated R12-R15.
// ---------------------------------------------------------------------------
#define HEADW 3712

__global__ __launch_bounds__(64, 8)
void attn_kernel(const float* __restrict__ mask)
{
    __shared__ uint32_t smw[HEADW];     // 14848 B
    const int b  = blockIdx.x;
    const int gh = blockIdx.y;
    const int tid = threadIdx.x;
    const __half* qkv = reinterpret_cast<const __half*>(g_qkv_h);
    __half* attout = reinterpret_cast<__half*>(g_att_h);
    const uint32_t sbase = smem_u32(smw);

    // ---- Q/K staging via cp.async: 392 16B tasks ----
    for (int f = tid; f < 392; f += 64) {
        const int sel = f / 196, r2 = f % 196;
        const int i = r2 >> 2, c = r2 & 3;
        CP_ASYNC16(sbase + (sel * 1280 + i * 20 + c * 4) * 4,
                   qkv + ((size_t)b * NTOK + i) * QKV_N + sel * C_DIM + gh * 32 + c * 8);
    }
    CP_COMMIT();

    // ---- V transpose (LDG overlaps cp.async DMA): 128 tasks ----
    for (int f = tid; f < 128; f += 64) {
        const int jp = f >> 2, dq = f & 3;
        uint4 lo4 = make_uint4(0, 0, 0, 0), hi4 = make_uint4(0, 0, 0, 0);
        const __half* basep = qkv + ((size_t)b * NTOK + 2 * jp) * QKV_N
                              + 2 * C_DIM + gh * 32 + dq * 8;
        if (2 * jp     < NTOK) lo4 = *reinterpret_cast<const uint4*>(basep);
        if (2 * jp + 1 < NTOK) hi4 = *reinterpret_cast<const uint4*>(basep + QKV_N);
        const __half* lo = reinterpret_cast<const __half*>(&lo4);
        const __half* hi = reinterpret_cast<const __half*>(&hi4);
        uint32_t* Vh = smw + 2560;
#pragma unroll
        for (int t = 0; t < 8; t++) {
            __half2 hv = __halves2half2(lo[t], hi[t]);
            Vh[(dq * 8 + t) * 36 + jp] = *reinterpret_cast<uint32_t*>(&hv);
        }
    }
    CP_WAIT(0);
    __syncthreads();

    const int wid = tid >> 5, lane = tid & 31;
    const int g = lane >> 2, q = lane & 3;
    const int rowbase = wid * 32;
    const uint32_t* Qs = smw;
    const uint32_t* Ks = smw + 1280;
    const uint32_t* Vt = smw + 2560;

    // ---- S = Q K^T : 2 m-tiles x 8 n-tiles ----
    float s[2][8][4] = {};
#pragma unroll
    for (int ks = 0; ks < 2; ks++) {
        uint32_t a[2][4];
#pragma unroll
        for (int mtl = 0; mtl < 2; mtl++) {
            const int r = rowbase + mtl * 16 + g;
            a[mtl][0] = Qs[r * 20 + 8 * ks + q];
            a[mtl][1] = Qs[(r + 8) * 20 + 8 * ks + q];
            a[mtl][2] = Qs[r * 20 + 8 * ks + q + 4];
            a[mtl][3] = Qs[(r + 8) * 20 + 8 * ks + q + 4];
        }
#pragma unroll
        for (int nt = 0; nt < 8; nt++) {
            uint32_t bb[2];
            bb[0] = Ks[(8 * nt + g) * 20 + 8 * ks + q];
            bb[1] = Ks[(8 * nt + g) * 20 + 8 * ks + q + 4];
            mma_f16(s[0][nt], a[0], bb);
            mma_f16(s[1][nt], a[1], bb);
        }
    }

    // ---- scale + mask from global (L2-resident); invalid cols -> -1e30 ----
    const float scale = 0.17677669529663687f;
    const float* mrow = mask + (size_t)(b & (NWIN - 1)) * NTOK * NTOK;
#pragma unroll
    for (int mtl = 0; mtl < 2; mtl++) {
        const int r1 = rowbase + mtl * 16 + g;
        const float* m1 = mrow + min(r1, 48) * NTOK;
        const float* m2 = mrow + min(r1 + 8, 48) * NTOK;
#pragma unroll
        for (int nt = 0; nt < 8; nt++) {
            const int j0 = 8 * nt + 2 * q, j1 = j0 + 1;
            if (j0 < NTOK) {
                s[mtl][nt][0] = fmaf(s[mtl][nt][0], scale, m1[j0]);
                s[mtl][nt][2] = fmaf(s[mtl][nt][2], scale, m2[j0]);
            } else { s[mtl][nt][0] = -1e30f; s[mtl][nt][2] = -1e30f; }
            if (j1 < NTOK) {
                s[mtl][nt][1] = fmaf(s[mtl][nt][1], scale, m1[j1]);
                s[mtl][nt][3] = fmaf(s[mtl][nt][3], scale, m2[j1]);
            } else { s[mtl][nt][1] = -1e30f; s[mtl][nt][3] = -1e30f; }
        }
    }

    // ---- fragment softmax (shfl xor 1,2 within lane quads) ----
#pragma unroll
    for (int mtl = 0; mtl < 2; mtl++) {
        float mxA = -1e30f, mxB = -1e30f;
#pragma unroll
        for (int nt = 0; nt < 8; nt++) {
            mxA = fmaxf(mxA, fmaxf(s[mtl][nt][0], s[mtl][nt][1]));
            mxB = fmaxf(mxB, fmaxf(s[mtl][nt][2], s[mtl][nt][3]));
        }
        mxA = fmaxf(mxA, __shfl_xor_sync(0xFFFFFFFFu, mxA, 1));
        mxA = fmaxf(mxA, __shfl_xor_sync(0xFFFFFFFFu, mxA, 2));
        mxB = fmaxf(mxB, __shfl_xor_sync(0xFFFFFFFFu, mxB, 1));
        mxB = fmaxf(mxB, __shfl_xor_sync(0xFFFFFFFFu, mxB, 2));
        float sA = 0.f, sB = 0.f;
#pragma unroll
        for (int nt = 0; nt < 8; nt++) {
            s[mtl][nt][0] = __expf(s[mtl][nt][0] - mxA); sA += s[mtl][nt][0];
            s[mtl][nt][1] = __expf(s[mtl][nt][1] - mxA); sA += s[mtl][nt][1];
            s[mtl][nt][2] = __expf(s[mtl][nt][2] - mxB); sB += s[mtl][nt][2];
            s[mtl][nt][3] = __expf(s[mtl][nt][3] - mxB); sB += s[mtl][nt][3];
        }
        sA += __shfl_xor_sync(0xFFFFFFFFu, sA, 1);
        sA += __shfl_xor_sync(0xFFFFFFFFu, sA, 2);
        sB += __shfl_xor_sync(0xFFFFFFFFu, sB, 1);
        sB += __shfl_xor_sync(0xFFFFFFFFu, sB, 2);
        const float invA = 1.0f / sA, invB = 1.0f / sB;
#pragma unroll
        for (int nt = 0; nt < 8; nt++) {
            s[mtl][nt][0] *= invA; s[mtl][nt][1] *= invA;
            s[mtl][nt][2] *= invB; s[mtl][nt][3] *= invB;
        }
    }

    // ---- O = P V : repack S C-frags as PV A-frags ----
    float o[2][4][4] = {};
#pragma unroll
    for (int ks = 0; ks < 4; ks++) {
        uint32_t pa[2][4];
#pragma unroll
        for (int mtl = 0; mtl < 2; mtl++) {
            pa[mtl][0] = packh2(s[mtl][2 * ks][0],     s[mtl][2 * ks][1]);
            pa[mtl][1] = packh2(s[mtl][2 * ks][2],     s[mtl][2 * ks][3]);
            pa[mtl][2] = packh2(s[mtl][2 * ks + 1][0], s[mtl][2 * ks + 1][1]);
            pa[mtl][3] = packh2(s[mtl][2 * ks + 1][2], s[mtl][2 * ks + 1][3]);
        }
#pragma unroll
        for (int nt2 = 0; nt2 < 4; nt2++) {
            uint32_t bb[2];
            bb[0] = Vt[(8 * nt2 + g) * 36 + 8 * ks + q];
            bb[1] = Vt[(8 * nt2 + g) * 36 + 8 * ks + q + 4];
            mma_f16(o[0][nt2], pa[0], bb);
            mma_f16(o[1][nt2], pa[1], bb);
        }
    }

    // ---- store valid rows as fp16 ----
#pragma unroll
    for (int mtl = 0; mtl < 2; mtl++) {
        const int r1 = rowbase + mtl * 16 + g, r2 = r1 + 8;
#pragma unroll
        for (int nt2 = 0; nt2 < 4; nt2++) {
            const int col = gh * 32 + 8 * nt2 + 2 * q;
            if (r1 < NTOK)
                *reinterpret_cast<uint32_t*>(
                    attout + ((size_t)b * NTOK + r1) * C_DIM + col) =
                    packh2(o[mtl][nt2][0], o[mtl][nt2][1]);
            if (r2 < NTOK)
                *reinterpret_cast<uint32_t*>(
                    attout + ((size_t)b * NTOK + r2) * C_DIM + col) =
                    packh2(o[mtl][nt2][2], o[mtl][nt2][3]);
        }
    }
}

// ---------------------------------------------------------------------------
// Launch pipeline
// ---------------------------------------------------------------------------
extern "C" void kernel_launch(void* const* d_in, const int* in_sizes, int n_in,
                              void* d_out, int out_size)
{
    const float* x      = (const float*)d_in[0];
    const float* mask   = (const float*)d_in[1];
    const float* w_qkv  = (const float*)d_in[2];
    const float* w_proj = (const float*)d_in[3];
    const float* b_proj = (const float*)d_in[4];
    float* out = (float*)d_out;

    void *xh_r, *qkv_r, *att_r, *wq_r, *wp_r;
    cudaGetSymbolAddress(&xh_r,  g_x_h);
    cudaGetSymbolAddress(&qkv_r, g_qkv_h);
    cudaGetSymbolAddress(&att_r, g_att_h);
    cudaGetSymbolAddress(&wq_r,  g_wqkvT_h);
    cudaGetSymbolAddress(&wp_r,  g_wprojT_h);
    __half* xh    = (__half*)xh_r;
    __half* qkvp  = (__half*)qkv_r;
    __half* attp  = (__half*)att_r;
    __half* wqkvT = (__half*)wq_r;
    __half* wprojT = (__half*)wp_r;

    cudaFuncSetAttribute(mma_gemm<__half>,
                         cudaFuncAttributeMaxDynamicSharedMemorySize, GEMM_SMEM);
    cudaFuncSetAttribute(mma_gemm<float>,
                         cudaFuncAttributeMaxDynamicSharedMemorySize, GEMM_SMEM);

    // One-time conversions
    const int n4 = M_TOTAL * KDIM / 4;
    conv_f32_f16<<<(n4 + 255) / 256, 256>>>(x, xh, n4);
    const int nt2 = KDIM * QKV_N + KDIM * C_DIM;
    conv_transpose2<<<(nt2 + 255) / 256, 256>>>(w_qkv, wqkvT, w_proj, wprojT);

    // QKV: [200704,192] @ [192,576] -> fp16
    mma_gemm<__half><<<dim3(QKV_N / BN, M_TOTAL / BM), 256, GEMM_SMEM>>>(
        xh, wqkvT, qkvp, nullptr, QKV_N);

    // Attention: (window, head) grid, 64-thread CTAs
    attn_kernel<<<dim3(B_WIN, NHEAD), 64>>>(mask);

    // Proj: [200704,192] @ [192,192] + bias -> fp32 output
    mma_gemm<float><<<dim3(C_DIM / BN, M_TOTAL / BM), 256, GEMM_SMEM>>>(
        attp, wprojT, out, b_proj, C_DIM);
}